// round 1
// baseline (speedup 1.0000x reference)
#include <cuda_runtime.h>
#include <math.h>

#define BATCH 4
#define SEQ   2048
#define DIM   1024
#define NH    16
#define HD    64
#define MROWS (BATCH*SEQ)

// Scratch (allocation-free rule: __device__ globals)
__device__ float g_Q[BATCH*NH*SEQ*HD];
__device__ float g_K[BATCH*NH*SEQ*HD];
__device__ float g_V[BATCH*NH*SEQ*HD];
__device__ float g_ctx[(size_t)MROWS*DIM];

// ---------------------------------------------------------------------------
// SGEMM (NT): C[M=8192][N=1024] = X @ W^T + bias
// mode 0/1/2: write head-major layout into g_Q/g_K/g_V
// mode 3:     X = g_ctx, write row-major into dst_param (d_out)
// 128x128 block, BK=8, 256 threads, 8x8 microtile.
// ---------------------------------------------------------------------------
__global__ __launch_bounds__(256, 2)
void sgemm_nt(const float* __restrict__ Xin, const float* __restrict__ W,
              const float* __restrict__ bias, float* __restrict__ dst_param,
              int mode)
{
    const int K = DIM, N = DIM;
    __shared__ __align__(16) float As[8][128];
    __shared__ __align__(16) float Bs[8][128];

    const float* X = (mode == 3) ? g_ctx : Xin;

    int tid  = threadIdx.x;
    int m0   = blockIdx.y * 128;
    int n0   = blockIdx.x * 128;
    int arow = tid >> 1;
    int acol = (tid & 1) << 2;
    int ty   = tid >> 4, tx = tid & 15;

    const float* Xp = X + (size_t)(m0 + arow) * K + acol;
    const float* Wp = W + (size_t)(n0 + arow) * K + acol;

    float acc[8][8];
    #pragma unroll
    for (int i = 0; i < 8; i++)
        #pragma unroll
        for (int j = 0; j < 8; j++) acc[i][j] = 0.0f;

    for (int kt = 0; kt < K; kt += 8) {
        float4 av = *(const float4*)(Xp + kt);
        float4 bv = *(const float4*)(Wp + kt);
        As[acol+0][arow] = av.x; As[acol+1][arow] = av.y;
        As[acol+2][arow] = av.z; As[acol+3][arow] = av.w;
        Bs[acol+0][arow] = bv.x; Bs[acol+1][arow] = bv.y;
        Bs[acol+2][arow] = bv.z; Bs[acol+3][arow] = bv.w;
        __syncthreads();
        #pragma unroll
        for (int k = 0; k < 8; k++) {
            float a[8], b[8];
            *(float4*)&a[0] = *(const float4*)&As[k][ty*8];
            *(float4*)&a[4] = *(const float4*)&As[k][ty*8+4];
            *(float4*)&b[0] = *(const float4*)&Bs[k][tx*8];
            *(float4*)&b[4] = *(const float4*)&Bs[k][tx*8+4];
            #pragma unroll
            for (int i = 0; i < 8; i++)
                #pragma unroll
                for (int j = 0; j < 8; j++)
                    acc[i][j] += a[i] * b[j];
        }
        __syncthreads();
    }

    float* dst;
    if      (mode == 0) dst = g_Q;
    else if (mode == 1) dst = g_K;
    else if (mode == 2) dst = g_V;
    else                dst = dst_param;

    int nc = n0 + tx * 8;
    float bloc[8];
    #pragma unroll
    for (int j = 0; j < 8; j++) bloc[j] = bias[nc + j];

    #pragma unroll
    for (int i = 0; i < 8; i++) {
        int m = m0 + ty * 8 + i;
        float o[8];
        #pragma unroll
        for (int j = 0; j < 8; j++) o[j] = acc[i][j] + bloc[j];
        float* p;
        if (mode == 3) {
            p = dst + (size_t)m * N + nc;
        } else {
            int b = m >> 11;          // m / 2048
            int s = m & 2047;
            int h = nc >> 6;          // head
            int d = nc & 63;
            p = dst + (((size_t)(b * NH + h) * SEQ + s) << 6) + d;
        }
        *(float4*)p       = make_float4(o[0], o[1], o[2], o[3]);
        *(float4*)(p + 4) = make_float4(o[4], o[5], o[6], o[7]);
    }
}

// ---------------------------------------------------------------------------
// RoPE (in-place on g_Q / g_K), faithful to reference:
//   x_rot = cat([-x[1::2], x[::2]]); out = x*cos + x_rot*sin
//   theta(s, e) = s * 10000^(-e/32), pair (e, e+32) shares theta.
// One warp per (bh, s) row of 64 floats.
// ---------------------------------------------------------------------------
__global__ void rope_kernel()
{
    int gw   = (blockIdx.x * blockDim.x + threadIdx.x) >> 5; // global warp = row
    int lane = threadIdx.x & 31;
    float* base = (blockIdx.y == 0) ? g_Q : g_K;
    int s = gw & (SEQ - 1);
    float* row = base + (size_t)gw * HD;

    float invf = (float)pow(10000.0, -(double)lane / 32.0);
    float sn, cs;
    sincosf((float)s * invf, &sn, &cs);

    float xe   = row[lane];
    float xe32 = row[lane + 32];
    float x2e  = row[2 * lane];
    float x2e1 = row[2 * lane + 1];
    __syncwarp();
    row[lane]      = xe   * cs - x2e1 * sn;
    row[lane + 32] = xe32 * cs + x2e  * sn;
}

// ---------------------------------------------------------------------------
// Flash attention, fp32, causal. BM=64 queries/CTA, BN=32 kv/tile, 128 thr.
// Thread (ty 0..15, tx 0..7): S microtile 4x4 (rows ty*4.., cols tx*4..),
// PV microtile 4x8 (rows ty*4.., dims tx*8..). Online softmax per row,
// row group = 8 consecutive lanes (shfl_xor 1/2/4).
// smem: Qs[k][r] 64x65, Ks[k][c] 64x33, Vs[c][d] 32x64, Ps[c][r] 32x65
//       = 41600 B (static).
// ---------------------------------------------------------------------------
__global__ __launch_bounds__(128)
void attn_kernel()
{
    __shared__ float Qs[64][65];
    __shared__ float Ks[64][33];
    __shared__ float Vs[32][64];
    __shared__ float Ps[32][65];

    int tid = threadIdx.x;
    int ty  = tid >> 3, tx = tid & 7;
    int bh  = blockIdx.y;
    int q0  = blockIdx.x << 6;

    const float* Qb = g_Q + (size_t)bh * SEQ * HD;
    const float* Kb = g_K + (size_t)bh * SEQ * HD;
    const float* Vb = g_V + (size_t)bh * SEQ * HD;

    // Load Q tile (transposed, pre-scaled by 1/sqrt(64))
    #pragma unroll
    for (int it = 0; it < 8; it++) {
        int idx = tid + it * 128;           // float4 index 0..1023
        int r = idx >> 4, kq = (idx & 15) << 2;
        float4 v = *(const float4*)(Qb + ((size_t)(q0 + r) << 6) + kq);
        Qs[kq+0][r] = v.x * 0.125f; Qs[kq+1][r] = v.y * 0.125f;
        Qs[kq+2][r] = v.z * 0.125f; Qs[kq+3][r] = v.w * 0.125f;
    }

    float m_i[4] = {-1e30f, -1e30f, -1e30f, -1e30f};
    float l_i[4] = {0.f, 0.f, 0.f, 0.f};
    float acc[4][8];
    #pragma unroll
    for (int i = 0; i < 4; i++)
        #pragma unroll
        for (int d = 0; d < 8; d++) acc[i][d] = 0.0f;

    int ntiles = (blockIdx.x + 1) * 2;
    for (int t = 0; t < ntiles; t++) {
        int k0 = t << 5;
        __syncthreads();   // protect Ks/Vs/Ps from previous iteration readers
        #pragma unroll
        for (int it = 0; it < 4; it++) {
            int idx = tid + it * 128;       // float4 index 0..511
            int c = idx >> 4, kq = (idx & 15) << 2;
            float4 kv = *(const float4*)(Kb + ((size_t)(k0 + c) << 6) + kq);
            Ks[kq+0][c] = kv.x; Ks[kq+1][c] = kv.y;
            Ks[kq+2][c] = kv.z; Ks[kq+3][c] = kv.w;
            float4 vv = *(const float4*)(Vb + ((size_t)(k0 + c) << 6) + kq);
            *(float4*)&Vs[c][kq] = vv;
        }
        __syncthreads();

        // S = Q K^T (scaled)
        float sc[4][4];
        #pragma unroll
        for (int i = 0; i < 4; i++)
            #pragma unroll
            for (int j = 0; j < 4; j++) sc[i][j] = 0.0f;
        #pragma unroll 8
        for (int k = 0; k < 64; k++) {
            float a0 = Qs[k][ty*4+0], a1 = Qs[k][ty*4+1];
            float a2 = Qs[k][ty*4+2], a3 = Qs[k][ty*4+3];
            float b0 = Ks[k][tx*4+0], b1 = Ks[k][tx*4+1];
            float b2 = Ks[k][tx*4+2], b3 = Ks[k][tx*4+3];
            sc[0][0] += a0*b0; sc[0][1] += a0*b1; sc[0][2] += a0*b2; sc[0][3] += a0*b3;
            sc[1][0] += a1*b0; sc[1][1] += a1*b1; sc[1][2] += a1*b2; sc[1][3] += a1*b3;
            sc[2][0] += a2*b0; sc[2][1] += a2*b1; sc[2][2] += a2*b2; sc[2][3] += a2*b3;
            sc[3][0] += a3*b0; sc[3][1] += a3*b1; sc[3][2] += a3*b2; sc[3][3] += a3*b3;
        }

        // causal mask (only diagonal-adjacent tiles need it)
        if (t >= 2 * (int)blockIdx.x) {
            #pragma unroll
            for (int i = 0; i < 4; i++)
                #pragma unroll
                for (int j = 0; j < 4; j++)
                    if (k0 + tx*4 + j > q0 + ty*4 + i) sc[i][j] = -1e30f;
        }

        // online softmax per row; write P transposed to smem
        #pragma unroll
        for (int i = 0; i < 4; i++) {
            float mloc = fmaxf(fmaxf(sc[i][0], sc[i][1]), fmaxf(sc[i][2], sc[i][3]));
            mloc = fmaxf(mloc, __shfl_xor_sync(0xffffffffu, mloc, 1));
            mloc = fmaxf(mloc, __shfl_xor_sync(0xffffffffu, mloc, 2));
            mloc = fmaxf(mloc, __shfl_xor_sync(0xffffffffu, mloc, 4));
            float mnew  = fmaxf(m_i[i], mloc);
            float scale = expf(m_i[i] - mnew);
            float p0 = expf(sc[i][0] - mnew);
            float p1 = expf(sc[i][1] - mnew);
            float p2 = expf(sc[i][2] - mnew);
            float p3 = expf(sc[i][3] - mnew);
            float ls = p0 + p1 + p2 + p3;
            ls += __shfl_xor_sync(0xffffffffu, ls, 1);
            ls += __shfl_xor_sync(0xffffffffu, ls, 2);
            ls += __shfl_xor_sync(0xffffffffu, ls, 4);
            l_i[i] = l_i[i] * scale + ls;
            #pragma unroll
            for (int d = 0; d < 8; d++) acc[i][d] *= scale;
            m_i[i] = mnew;
            Ps[tx*4+0][ty*4+i] = p0;
            Ps[tx*4+1][ty*4+i] = p1;
            Ps[tx*4+2][ty*4+i] = p2;
            Ps[tx*4+3][ty*4+i] = p3;
        }
        __syncthreads();

        // acc += P V
        #pragma unroll 4
        for (int j = 0; j < 32; j++) {
            float a0 = Ps[j][ty*4+0], a1 = Ps[j][ty*4+1];
            float a2 = Ps[j][ty*4+2], a3 = Ps[j][ty*4+3];
            float4 b0 = *(const float4*)&Vs[j][tx*8];
            float4 b1 = *(const float4*)&Vs[j][tx*8+4];
            acc[0][0] += a0*b0.x; acc[0][1] += a0*b0.y; acc[0][2] += a0*b0.z; acc[0][3] += a0*b0.w;
            acc[0][4] += a0*b1.x; acc[0][5] += a0*b1.y; acc[0][6] += a0*b1.z; acc[0][7] += a0*b1.w;
            acc[1][0] += a1*b0.x; acc[1][1] += a1*b0.y; acc[1][2] += a1*b0.z; acc[1][3] += a1*b0.w;
            acc[1][4] += a1*b1.x; acc[1][5] += a1*b1.y; acc[1][6] += a1*b1.z; acc[1][7] += a1*b1.w;
            acc[2][0] += a2*b0.x; acc[2][1] += a2*b0.y; acc[2][2] += a2*b0.z; acc[2][3] += a2*b0.w;
            acc[2][4] += a2*b1.x; acc[2][5] += a2*b1.y; acc[2][6] += a2*b1.z; acc[2][7] += a2*b1.w;
            acc[3][0] += a3*b0.x; acc[3][1] += a3*b0.y; acc[3][2] += a3*b0.z; acc[3][3] += a3*b0.w;
            acc[3][4] += a3*b1.x; acc[3][5] += a3*b1.y; acc[3][6] += a3*b1.z; acc[3][7] += a3*b1.w;
        }
    }

    // epilogue: normalize, write ctx in [b][s][h*64+d] row-major layout
    int b = bh >> 4, h = bh & 15;
    #pragma unroll
    for (int i = 0; i < 4; i++) {
        float inv  = 1.0f / l_i[i];
        int   srow = q0 + ty*4 + i;
        float* p = g_ctx + ((size_t)(b * SEQ + srow) << 10) + (h << 6) + tx*8;
        *(float4*)p       = make_float4(acc[i][0]*inv, acc[i][1]*inv, acc[i][2]*inv, acc[i][3]*inv);
        *(float4*)(p + 4) = make_float4(acc[i][4]*inv, acc[i][5]*inv, acc[i][6]*inv, acc[i][7]*inv);
    }
}

// ---------------------------------------------------------------------------
extern "C" void kernel_launch(void* const* d_in, const int* in_sizes, int n_in,
                              void* d_out, int out_size)
{
    const float* query = (const float*)d_in[0];
    const float* key   = (const float*)d_in[1];
    const float* value = (const float*)d_in[2];
    // d_in[3] = mask (causal tril) — applied analytically in attn_kernel
    const float* w_q = (const float*)d_in[4];
    const float* b_q = (const float*)d_in[5];
    const float* w_k = (const float*)d_in[6];
    const float* b_k = (const float*)d_in[7];
    const float* w_v = (const float*)d_in[8];
    const float* b_v = (const float*)d_in[9];
    const float* w_o = (const float*)d_in[10];
    const float* b_o = (const float*)d_in[11];
    float* out = (float*)d_out;

    dim3 ggrid(DIM / 128, MROWS / 128);   // (8, 64)
    sgemm_nt<<<ggrid, 256>>>(query, w_q, b_q, nullptr, 0);
    sgemm_nt<<<ggrid, 256>>>(key,   w_k, b_k, nullptr, 1);
    sgemm_nt<<<ggrid, 256>>>(value, w_v, b_v, nullptr, 2);

    // RoPE on Q and K: one warp per row, 8 warps/block
    rope_kernel<<<dim3(BATCH*NH*SEQ/8, 2), 256>>>();

    // attention: grid (q-tiles=32, bh=64)
    attn_kernel<<<dim3(SEQ/64, BATCH*NH), 128>>>();

    // output projection -> d_out
    sgemm_nt<<<ggrid, 256>>>(nullptr, w_o, b_o, out, 3);
}

// round 3
// speedup vs baseline: 1.2869x; 1.2869x over previous
#include <cuda_runtime.h>
#include <cuda_bf16.h>
#include <math.h>
#include <stdint.h>

#define BATCH 4
#define SEQ   2048
#define DIM   1024
#define NH    16
#define HD    64
#define MROWS (BATCH*SEQ)

// ---------------------------------------------------------------------------
// Scratch (__device__ globals; allocation-free rule)
// ---------------------------------------------------------------------------
__device__ float g_Q[BATCH*NH*SEQ*HD];
__device__ float g_K[BATCH*NH*SEQ*HD];
__device__ float g_V[BATCH*NH*SEQ*HD];
__device__ float g_ctx[(size_t)MROWS*DIM];
// bf16x3 split buffers: A2 = [Xhi | Xlo] (row width 2048), B2 = [Whi | Wlo]
__device__ __nv_bfloat16 g_A2[(size_t)MROWS*2048];
__device__ __nv_bfloat16 g_B2[(size_t)DIM*2048];

__device__ __forceinline__ uint32_t smem_u32(const void* p) {
    uint32_t a;
    asm("{ .reg .u64 t; cvta.to.shared.u64 t, %1; cvt.u32.u64 %0, t; }" : "=r"(a) : "l"(p));
    return a;
}

#define LDMATRIX_X4(r0, r1, r2, r3, addr) \
    asm volatile("ldmatrix.sync.aligned.m8n8.x4.shared.b16 {%0,%1,%2,%3}, [%4];" \
        : "=r"(r0), "=r"(r1), "=r"(r2), "=r"(r3) : "r"(addr))

#define MMA_BF16(c, a, b0v, b1v) \
    asm volatile("mma.sync.aligned.m16n8k16.row.col.f32.bf16.bf16.f32 " \
        "{%0,%1,%2,%3}, {%4,%5,%6,%7}, {%8,%9}, {%0,%1,%2,%3};" \
        : "+f"((c)[0]), "+f"((c)[1]), "+f"((c)[2]), "+f"((c)[3]) \
        : "r"((a)[0]), "r"((a)[1]), "r"((a)[2]), "r"((a)[3]), "r"(b0v), "r"(b1v))

#define CP_ASYNC16(dst, src) \
    asm volatile("cp.async.cg.shared.global [%0], [%1], 16;" :: "r"(dst), "l"(src))
#define CP_COMMIT() asm volatile("cp.async.commit_group;" ::: "memory")
#define CP_WAIT0()  asm volatile("cp.async.wait_group 0;" ::: "memory")

// ---------------------------------------------------------------------------
// f32 -> bf16 hi/lo split. which: 0 -> g_A2, 1 -> g_B2. in==nullptr -> g_ctx.
// out[r][k] = hi, out[r][1024+k] = lo   (row width 2048 bf16)
// ---------------------------------------------------------------------------
struct bf4 { __nv_bfloat162 a, b; };
__global__ void split_kernel(const float* __restrict__ in, int nrows, int which)
{
    const float* src = in ? in : g_ctx;
    int i = blockIdx.x * blockDim.x + threadIdx.x;    // float4 index
    if (i >= nrows * 256) return;
    int r = i >> 8, c4 = i & 255;
    float4 v = ((const float4*)src)[i];
    __nv_bfloat16 h0 = __float2bfloat16(v.x);
    __nv_bfloat16 h1 = __float2bfloat16(v.y);
    __nv_bfloat16 h2 = __float2bfloat16(v.z);
    __nv_bfloat16 h3 = __float2bfloat16(v.w);
    __nv_bfloat16 l0 = __float2bfloat16(v.x - __bfloat162float(h0));
    __nv_bfloat16 l1 = __float2bfloat16(v.y - __bfloat162float(h1));
    __nv_bfloat16 l2 = __float2bfloat16(v.z - __bfloat162float(h2));
    __nv_bfloat16 l3 = __float2bfloat16(v.w - __bfloat162float(h3));
    __nv_bfloat16* out = which ? g_B2 : g_A2;
    size_t base = (size_t)r * 2048 + c4 * 4;
    bf4 hv; hv.a = __nv_bfloat162(h0, h1); hv.b = __nv_bfloat162(h2, h3);
    bf4 lv; lv.a = __nv_bfloat162(l0, l1); lv.b = __nv_bfloat162(l2, l3);
    *(bf4*)(out + base)        = hv;
    *(bf4*)(out + base + 1024) = lv;
}

// ---------------------------------------------------------------------------
// mma.sync bf16x3 GEMM: C[8192x1024] = A @ W^T + bias over K'=3072
//   segments: [0,1024): Xhi*Whi  [1024,2048): Xlo*Whi  [2048,3072): Xhi*Wlo
// CTA 128x128, 8 warps (2m x 4n), warp tile 64x32, m16n8k16 HMMA.
// BK=64, cp.async double buffered. Pitch 72 bf16 (144B) -> conflict-free.
// mode 0/1/2 -> head-major g_Q/g_K/g_V;  mode 3 -> row-major dst_param.
// ---------------------------------------------------------------------------
#define PITCH    72
#define STAGE_B  (128*PITCH*2)          // 18432 bytes per tile-stage
#define GEMM_SMEM (4*STAGE_B)            // A0 A1 B0 B1 = 73728

__global__ __launch_bounds__(256)
void gemm_mma(const float* __restrict__ bias, float* __restrict__ dst_param, int mode)
{
    extern __shared__ __align__(16) char sm[];
    uint32_t sb = smem_u32(sm);

    int tid  = threadIdx.x;
    int lane = tid & 31;
    int wid  = tid >> 5;
    int wm   = wid & 1;          // 0..1 (m)
    int wn   = wid >> 1;         // 0..3 (n)
    int m0 = blockIdx.y << 7, n0 = blockIdx.x << 7;

    // lane-derived ldmatrix addressing
    int lr = ((lane >> 3) & 1) * 8 + (lane & 7);   // row within 16
    int lk = (lane >> 4) * 8;                      // k offset 0/8

    float c[4][4][4];
    #pragma unroll
    for (int mf = 0; mf < 4; mf++)
        #pragma unroll
        for (int nf = 0; nf < 4; nf++)
            #pragma unroll
            for (int v = 0; v < 4; v++) c[mf][nf][v] = 0.0f;

    auto load_stage = [&](int t, int buf) {
        int kp = t << 6;
        int ac = kp & 2047;
        int bc = kp - ((kp >= 1024) ? 1024 : 0);
        const __nv_bfloat16* Ab = g_A2 + (size_t)m0 * 2048 + ac;
        const __nv_bfloat16* Bb = g_B2 + (size_t)n0 * 2048 + bc;
        uint32_t sa  = sb + buf * STAGE_B;
        uint32_t sbb = sb + 2 * STAGE_B + buf * STAGE_B;
        #pragma unroll
        for (int it = 0; it < 4; it++) {
            int id = tid + (it << 8);
            int r = id >> 3, ch = id & 7;
            CP_ASYNC16(sa  + r * 144 + (ch << 4), Ab + (size_t)r * 2048 + (ch << 3));
            CP_ASYNC16(sbb + r * 144 + (ch << 4), Bb + (size_t)r * 2048 + (ch << 3));
        }
        CP_COMMIT();
    };

    load_stage(0, 0);

    #pragma unroll 1
    for (int t = 0; t < 48; t++) {
        CP_WAIT0();
        __syncthreads();
        if (t + 1 < 48) load_stage(t + 1, (t + 1) & 1);

        uint32_t sa  = sb + (t & 1) * STAGE_B;
        uint32_t sbb = sb + 2 * STAGE_B + (t & 1) * STAGE_B;

        #pragma unroll
        for (int kk = 0; kk < 64; kk += 16) {
            uint32_t a[4][4];
            #pragma unroll
            for (int mf = 0; mf < 4; mf++) {
                uint32_t ad = sa + (uint32_t)(wm * 64 + mf * 16 + lr) * 144 + (kk + lk) * 2;
                LDMATRIX_X4(a[mf][0], a[mf][1], a[mf][2], a[mf][3], ad);
            }
            uint32_t b[2][4];
            #pragma unroll
            for (int nb = 0; nb < 2; nb++) {
                uint32_t bd = sbb + (uint32_t)(wn * 32 + nb * 16 + lr) * 144 + (kk + lk) * 2;
                LDMATRIX_X4(b[nb][0], b[nb][1], b[nb][2], b[nb][3], bd);
            }
            #pragma unroll
            for (int mf = 0; mf < 4; mf++) {
                #pragma unroll
                for (int nf = 0; nf < 4; nf++) {
                    int nb = nf >> 1;
                    uint32_t b0 = (nf & 1) ? b[nb][1] : b[nb][0];
                    uint32_t b1 = (nf & 1) ? b[nb][3] : b[nb][2];
                    MMA_BF16(c[mf][nf], a[mf], b0, b1);
                }
            }
        }
        __syncthreads();
    }

    // epilogue: add bias, write out
    int rq = lane >> 2, cq = (lane & 3) * 2;
    float2 bv[4];
    #pragma unroll
    for (int nf = 0; nf < 4; nf++) {
        int col = n0 + wn * 32 + nf * 8 + cq;
        bv[nf] = make_float2(bias[col], bias[col + 1]);
    }

    #pragma unroll
    for (int mf = 0; mf < 4; mf++) {
        #pragma unroll
        for (int nf = 0; nf < 4; nf++) {
            int r   = m0 + wm * 64 + mf * 16 + rq;
            int col = n0 + wn * 32 + nf * 8 + cq;
            float2 lo = make_float2(c[mf][nf][0] + bv[nf].x, c[mf][nf][1] + bv[nf].y);
            float2 hi = make_float2(c[mf][nf][2] + bv[nf].x, c[mf][nf][3] + bv[nf].y);
            if (mode == 3) {
                *(float2*)(dst_param + (size_t)r * 1024 + col)       = lo;
                *(float2*)(dst_param + (size_t)(r + 8) * 1024 + col) = hi;
            } else {
                float* g = (mode == 0) ? g_Q : (mode == 1) ? g_K : g_V;
                int h = col >> 6, d0 = col & 63;
                int b1 = r >> 11, s1 = r & 2047;
                *(float2*)(g + (((size_t)(b1 * NH + h) * SEQ + s1) << 6) + d0) = lo;
                int s2 = (r + 8) & 2047;
                *(float2*)(g + (((size_t)(b1 * NH + h) * SEQ + s2) << 6) + d0) = hi;
            }
        }
    }
}

// ---------------------------------------------------------------------------
// RoPE (in-place on g_Q / g_K)
// ---------------------------------------------------------------------------
__global__ void rope_kernel()
{
    int gw   = (blockIdx.x * blockDim.x + threadIdx.x) >> 5;
    int lane = threadIdx.x & 31;
    float* base = (blockIdx.y == 0) ? g_Q : g_K;
    int s = gw & (SEQ - 1);
    float* row = base + (size_t)gw * HD;

    float invf = (float)pow(10000.0, -(double)lane / 32.0);
    float sn, cs;
    sincosf((float)s * invf, &sn, &cs);

    float xe   = row[lane];
    float xe32 = row[lane + 32];
    float x2e  = row[2 * lane];
    float x2e1 = row[2 * lane + 1];
    __syncwarp();
    row[lane]      = xe   * cs - x2e1 * sn;
    row[lane + 32] = xe32 * cs + x2e  * sn;
}

// ---------------------------------------------------------------------------
// Flash attention, fp32, causal. BM=64, BN=32, 128 threads.
// ---------------------------------------------------------------------------
__global__ __launch_bounds__(128)
void attn_kernel()
{
    __shared__ __align__(16) float Qs[64][68];
    __shared__ __align__(16) float Ks[64][36];
    __shared__ __align__(16) float Vs[32][64];
    __shared__ __align__(16) float Ps[32][68];

    int tid = threadIdx.x;
    int ty  = tid >> 3, tx = tid & 7;
    int bh  = blockIdx.y;
    int q0  = blockIdx.x << 6;

    const float* Qb = g_Q + (size_t)bh * SEQ * HD;
    const float* Kb = g_K + (size_t)bh * SEQ * HD;
    const float* Vb = g_V + (size_t)bh * SEQ * HD;

    #pragma unroll
    for (int it = 0; it < 8; it++) {
        int idx = tid + it * 128;
        int r = idx >> 4, kq = (idx & 15) << 2;
        float4 v = *(const float4*)(Qb + ((size_t)(q0 + r) << 6) + kq);
        Qs[kq+0][r] = v.x * 0.125f; Qs[kq+1][r] = v.y * 0.125f;
        Qs[kq+2][r] = v.z * 0.125f; Qs[kq+3][r] = v.w * 0.125f;
    }

    float m_i[4] = {-1e30f, -1e30f, -1e30f, -1e30f};
    float l_i[4] = {0.f, 0.f, 0.f, 0.f};
    float acc[4][8];
    #pragma unroll
    for (int i = 0; i < 4; i++)
        #pragma unroll
        for (int d = 0; d < 8; d++) acc[i][d] = 0.0f;

    int ntiles = (blockIdx.x + 1) * 2;
    for (int t = 0; t < ntiles; t++) {
        int k0 = t << 5;
        __syncthreads();
        #pragma unroll
        for (int it = 0; it < 4; it++) {
            int idx = tid + it * 128;
            int cc = idx >> 4, kq = (idx & 15) << 2;
            float4 kv = *(const float4*)(Kb + ((size_t)(k0 + cc) << 6) + kq);
            Ks[kq+0][cc] = kv.x; Ks[kq+1][cc] = kv.y;
            Ks[kq+2][cc] = kv.z; Ks[kq+3][cc] = kv.w;
            float4 vv = *(const float4*)(Vb + ((size_t)(k0 + cc) << 6) + kq);
            *(float4*)&Vs[cc][kq] = vv;
        }
        __syncthreads();

        float sc[4][4];
        #pragma unroll
        for (int i = 0; i < 4; i++)
            #pragma unroll
            for (int j = 0; j < 4; j++) sc[i][j] = 0.0f;
        #pragma unroll 8
        for (int k = 0; k < 64; k++) {
            float4 av = *(const float4*)&Qs[k][ty*4];
            float4 bvv = *(const float4*)&Ks[k][tx*4];
            sc[0][0] += av.x*bvv.x; sc[0][1] += av.x*bvv.y; sc[0][2] += av.x*bvv.z; sc[0][3] += av.x*bvv.w;
            sc[1][0] += av.y*bvv.x; sc[1][1] += av.y*bvv.y; sc[1][2] += av.y*bvv.z; sc[1][3] += av.y*bvv.w;
            sc[2][0] += av.z*bvv.x; sc[2][1] += av.z*bvv.y; sc[2][2] += av.z*bvv.z; sc[2][3] += av.z*bvv.w;
            sc[3][0] += av.w*bvv.x; sc[3][1] += av.w*bvv.y; sc[3][2] += av.w*bvv.z; sc[3][3] += av.w*bvv.w;
        }

        if (t >= 2 * (int)blockIdx.x) {
            #pragma unroll
            for (int i = 0; i < 4; i++)
                #pragma unroll
                for (int j = 0; j < 4; j++)
                    if (k0 + tx*4 + j > q0 + ty*4 + i) sc[i][j] = -1e30f;
        }

        #pragma unroll
        for (int i = 0; i < 4; i++) {
            float mloc = fmaxf(fmaxf(sc[i][0], sc[i][1]), fmaxf(sc[i][2], sc[i][3]));
            mloc = fmaxf(mloc, __shfl_xor_sync(0xffffffffu, mloc, 1));
            mloc = fmaxf(mloc, __shfl_xor_sync(0xffffffffu, mloc, 2));
            mloc = fmaxf(mloc, __shfl_xor_sync(0xffffffffu, mloc, 4));
            float mnew  = fmaxf(m_i[i], mloc);
            float scale = __expf(m_i[i] - mnew);
            float p0 = __expf(sc[i][0] - mnew);
            float p1 = __expf(sc[i][1] - mnew);
            float p2 = __expf(sc[i][2] - mnew);
            float p3 = __expf(sc[i][3] - mnew);
            float ls = p0 + p1 + p2 + p3;
            ls += __shfl_xor_sync(0xffffffffu, ls, 1);
            ls += __shfl_xor_sync(0xffffffffu, ls, 2);
            ls += __shfl_xor_sync(0xffffffffu, ls, 4);
            l_i[i] = l_i[i] * scale + ls;
            #pragma unroll
            for (int d = 0; d < 8; d++) acc[i][d] *= scale;
            m_i[i] = mnew;
            Ps[tx*4+0][ty*4+i] = p0;
            Ps[tx*4+1][ty*4+i] = p1;
            Ps[tx*4+2][ty*4+i] = p2;
            Ps[tx*4+3][ty*4+i] = p3;
        }
        __syncthreads();

        #pragma unroll 4
        for (int j = 0; j < 32; j++) {
            float4 pa = *(const float4*)&Ps[j][ty*4];
            float4 b0 = *(const float4*)&Vs[j][tx*8];
            float4 b1 = *(const float4*)&Vs[j][tx*8+4];
            acc[0][0] += pa.x*b0.x; acc[0][1] += pa.x*b0.y; acc[0][2] += pa.x*b0.z; acc[0][3] += pa.x*b0.w;
            acc[0][4] += pa.x*b1.x; acc[0][5] += pa.x*b1.y; acc[0][6] += pa.x*b1.z; acc[0][7] += pa.x*b1.w;
            acc[1][0] += pa.y*b0.x; acc[1][1] += pa.y*b0.y; acc[1][2] += pa.y*b0.z; acc[1][3] += pa.y*b0.w;
            acc[1][4] += pa.y*b1.x; acc[1][5] += pa.y*b1.y; acc[1][6] += pa.y*b1.z; acc[1][7] += pa.y*b1.w;
            acc[2][0] += pa.z*b0.x; acc[2][1] += pa.z*b0.y; acc[2][2] += pa.z*b0.z; acc[2][3] += pa.z*b0.w;
            acc[2][4] += pa.z*b1.x; acc[2][5] += pa.z*b1.y; acc[2][6] += pa.z*b1.z; acc[2][7] += pa.z*b1.w;
            acc[3][0] += pa.w*b0.x; acc[3][1] += pa.w*b0.y; acc[3][2] += pa.w*b0.z; acc[3][3] += pa.w*b0.w;
            acc[3][4] += pa.w*b1.x; acc[3][5] += pa.w*b1.y; acc[3][6] += pa.w*b1.z; acc[3][7] += pa.w*b1.w;
        }
    }

    int b = bh >> 4, h = bh & 15;
    #pragma unroll
    for (int i = 0; i < 4; i++) {
        float inv  = 1.0f / l_i[i];
        int   srow = q0 + ty*4 + i;
        float* p = g_ctx + ((size_t)(b * SEQ + srow) << 10) + (h << 6) + tx*8;
        *(float4*)p       = make_float4(acc[i][0]*inv, acc[i][1]*inv, acc[i][2]*inv, acc[i][3]*inv);
        *(float4*)(p + 4) = make_float4(acc[i][4]*inv, acc[i][5]*inv, acc[i][6]*inv, acc[i][7]*inv);
    }
}

// ---------------------------------------------------------------------------
extern "C" void kernel_launch(void* const* d_in, const int* in_sizes, int n_in,
                              void* d_out, int out_size)
{
    const float* query = (const float*)d_in[0];
    const float* key   = (const float*)d_in[1];
    const float* value = (const float*)d_in[2];
    const float* w_q = (const float*)d_in[4];
    const float* b_q = (const float*)d_in[5];
    const float* w_k = (const float*)d_in[6];
    const float* b_k = (const float*)d_in[7];
    const float* w_v = (const float*)d_in[8];
    const float* b_v = (const float*)d_in[9];
    const float* w_o = (const float*)d_in[10];
    const float* b_o = (const float*)d_in[11];
    float* out = (float*)d_out;

    static int attr_set = 0;
    if (!attr_set) {
        cudaFuncSetAttribute(gemm_mma, cudaFuncAttributeMaxDynamicSharedMemorySize, GEMM_SMEM);
        attr_set = 1;
    }

    dim3 ggrid(DIM / 128, MROWS / 128);   // (8, 64)

    split_kernel<<<MROWS, 256>>>(query, MROWS, 0);
    split_kernel<<<DIM,   256>>>(w_q,   DIM,   1);
    gemm_mma<<<ggrid, 256, GEMM_SMEM>>>(b_q, nullptr, 0);

    split_kernel<<<MROWS, 256>>>(key, MROWS, 0);
    split_kernel<<<DIM,   256>>>(w_k, DIM,   1);
    gemm_mma<<<ggrid, 256, GEMM_SMEM>>>(b_k, nullptr, 1);

    split_kernel<<<MROWS, 256>>>(value, MROWS, 0);
    split_kernel<<<DIM,   256>>>(w_v,   DIM,   1);
    gemm_mma<<<ggrid, 256, GEMM_SMEM>>>(b_v, nullptr, 2);

    rope_kernel<<<dim3(BATCH*NH*SEQ/8, 2), 256>>>();
    attn_kernel<<<dim3(SEQ/64, BATCH*NH), 128>>>();

    split_kernel<<<MROWS, 256>>>(nullptr, MROWS, 0);   // g_ctx
    split_kernel<<<DIM,   256>>>(w_o,     DIM,   1);
    gemm_mma<<<ggrid, 256, GEMM_SMEM>>>(b_o, out, 3);
}

// round 4
// speedup vs baseline: 1.8389x; 1.4289x over previous
#include <cuda_runtime.h>
#include <cuda_bf16.h>
#include <cuda_fp16.h>
#include <math.h>
#include <stdint.h>

#define BATCH 4
#define SEQ   2048
#define DIM   1024
#define NH    16
#define HD    64
#define MROWS (BATCH*SEQ)

// ---------------------------------------------------------------------------
// Scratch (__device__ globals; allocation-free rule)
// ---------------------------------------------------------------------------
__device__ float g_Q[BATCH*NH*SEQ*HD];
__device__ float g_K[BATCH*NH*SEQ*HD];
__device__ float g_V[BATCH*NH*SEQ*HD];
__device__ float g_ctx[(size_t)MROWS*DIM];
// bf16x3 split buffers: A2 = [Xhi | Xlo] (row width 2048), B2 = [Whi | Wlo]
__device__ __nv_bfloat16 g_A2[(size_t)MROWS*2048];
__device__ __nv_bfloat16 g_B2[(size_t)DIM*2048];

__device__ __forceinline__ uint32_t smem_u32(const void* p) {
    uint32_t a;
    asm("{ .reg .u64 t; cvta.to.shared.u64 t, %1; cvt.u32.u64 %0, t; }" : "=r"(a) : "l"(p));
    return a;
}

#define LDMATRIX_X4(r0, r1, r2, r3, addr) \
    asm volatile("ldmatrix.sync.aligned.m8n8.x4.shared.b16 {%0,%1,%2,%3}, [%4];" \
        : "=r"(r0), "=r"(r1), "=r"(r2), "=r"(r3) : "r"(addr))

#define LDMATRIX_X4T(r0, r1, r2, r3, addr) \
    asm volatile("ldmatrix.sync.aligned.m8n8.x4.trans.shared.b16 {%0,%1,%2,%3}, [%4];" \
        : "=r"(r0), "=r"(r1), "=r"(r2), "=r"(r3) : "r"(addr))

#define MMA_BF16(c, a, b0v, b1v) \
    asm volatile("mma.sync.aligned.m16n8k16.row.col.f32.bf16.bf16.f32 " \
        "{%0,%1,%2,%3}, {%4,%5,%6,%7}, {%8,%9}, {%0,%1,%2,%3};" \
        : "+f"((c)[0]), "+f"((c)[1]), "+f"((c)[2]), "+f"((c)[3]) \
        : "r"((a)[0]), "r"((a)[1]), "r"((a)[2]), "r"((a)[3]), "r"(b0v), "r"(b1v))

#define MMA_F16(c, a, b0v, b1v) \
    asm volatile("mma.sync.aligned.m16n8k16.row.col.f32.f16.f16.f32 " \
        "{%0,%1,%2,%3}, {%4,%5,%6,%7}, {%8,%9}, {%0,%1,%2,%3};" \
        : "+f"((c)[0]), "+f"((c)[1]), "+f"((c)[2]), "+f"((c)[3]) \
        : "r"((a)[0]), "r"((a)[1]), "r"((a)[2]), "r"((a)[3]), "r"(b0v), "r"(b1v))

#define CP_ASYNC16(dst, src) \
    asm volatile("cp.async.cg.shared.global [%0], [%1], 16;" :: "r"(dst), "l"(src))
#define CP_COMMIT() asm volatile("cp.async.commit_group;" ::: "memory")
#define CP_WAIT0()  asm volatile("cp.async.wait_group 0;" ::: "memory")

__device__ __forceinline__ uint32_t h2u(__half2 h) { return *reinterpret_cast<uint32_t*>(&h); }

// ---------------------------------------------------------------------------
// f32 -> bf16 hi/lo split (for projection GEMMs)
// ---------------------------------------------------------------------------
struct bf4 { __nv_bfloat162 a, b; };
__global__ void split_kernel(const float* __restrict__ in, int nrows, int which)
{
    const float* src = in ? in : g_ctx;
    int i = blockIdx.x * blockDim.x + threadIdx.x;    // float4 index
    if (i >= nrows * 256) return;
    int r = i >> 8, c4 = i & 255;
    float4 v = ((const float4*)src)[i];
    __nv_bfloat16 h0 = __float2bfloat16(v.x);
    __nv_bfloat16 h1 = __float2bfloat16(v.y);
    __nv_bfloat16 h2 = __float2bfloat16(v.z);
    __nv_bfloat16 h3 = __float2bfloat16(v.w);
    __nv_bfloat16 l0 = __float2bfloat16(v.x - __bfloat162float(h0));
    __nv_bfloat16 l1 = __float2bfloat16(v.y - __bfloat162float(h1));
    __nv_bfloat16 l2 = __float2bfloat16(v.z - __bfloat162float(h2));
    __nv_bfloat16 l3 = __float2bfloat16(v.w - __bfloat162float(h3));
    __nv_bfloat16* out = which ? g_B2 : g_A2;
    size_t base = (size_t)r * 2048 + c4 * 4;
    bf4 hv; hv.a = __nv_bfloat162(h0, h1); hv.b = __nv_bfloat162(h2, h3);
    bf4 lv; lv.a = __nv_bfloat162(l0, l1); lv.b = __nv_bfloat162(l2, l3);
    *(bf4*)(out + base)        = hv;
    *(bf4*)(out + base + 1024) = lv;
}

// ---------------------------------------------------------------------------
// mma.sync bf16x3 GEMM (unchanged from R3, passing)
// ---------------------------------------------------------------------------
#define PITCH    72
#define STAGE_B  (128*PITCH*2)
#define GEMM_SMEM (4*STAGE_B)

__global__ __launch_bounds__(256)
void gemm_mma(const float* __restrict__ bias, float* __restrict__ dst_param, int mode)
{
    extern __shared__ __align__(16) char sm[];
    uint32_t sb = smem_u32(sm);

    int tid  = threadIdx.x;
    int lane = tid & 31;
    int wid  = tid >> 5;
    int wm   = wid & 1;
    int wn   = wid >> 1;
    int m0 = blockIdx.y << 7, n0 = blockIdx.x << 7;

    int lr = ((lane >> 3) & 1) * 8 + (lane & 7);
    int lk = (lane >> 4) * 8;

    float c[4][4][4];
    #pragma unroll
    for (int mf = 0; mf < 4; mf++)
        #pragma unroll
        for (int nf = 0; nf < 4; nf++)
            #pragma unroll
            for (int v = 0; v < 4; v++) c[mf][nf][v] = 0.0f;

    auto load_stage = [&](int t, int buf) {
        int kp = t << 6;
        int ac = kp & 2047;
        int bc = kp - ((kp >= 1024) ? 1024 : 0);
        const __nv_bfloat16* Ab = g_A2 + (size_t)m0 * 2048 + ac;
        const __nv_bfloat16* Bb = g_B2 + (size_t)n0 * 2048 + bc;
        uint32_t sa  = sb + buf * STAGE_B;
        uint32_t sbb = sb + 2 * STAGE_B + buf * STAGE_B;
        #pragma unroll
        for (int it = 0; it < 4; it++) {
            int id = tid + (it << 8);
            int r = id >> 3, ch = id & 7;
            CP_ASYNC16(sa  + r * 144 + (ch << 4), Ab + (size_t)r * 2048 + (ch << 3));
            CP_ASYNC16(sbb + r * 144 + (ch << 4), Bb + (size_t)r * 2048 + (ch << 3));
        }
        CP_COMMIT();
    };

    load_stage(0, 0);

    #pragma unroll 1
    for (int t = 0; t < 48; t++) {
        CP_WAIT0();
        __syncthreads();
        if (t + 1 < 48) load_stage(t + 1, (t + 1) & 1);

        uint32_t sa  = sb + (t & 1) * STAGE_B;
        uint32_t sbb = sb + 2 * STAGE_B + (t & 1) * STAGE_B;

        #pragma unroll
        for (int kk = 0; kk < 64; kk += 16) {
            uint32_t a[4][4];
            #pragma unroll
            for (int mf = 0; mf < 4; mf++) {
                uint32_t ad = sa + (uint32_t)(wm * 64 + mf * 16 + lr) * 144 + (kk + lk) * 2;
                LDMATRIX_X4(a[mf][0], a[mf][1], a[mf][2], a[mf][3], ad);
            }
            uint32_t b[2][4];
            #pragma unroll
            for (int nb = 0; nb < 2; nb++) {
                uint32_t bd = sbb + (uint32_t)(wn * 32 + nb * 16 + lr) * 144 + (kk + lk) * 2;
                LDMATRIX_X4(b[nb][0], b[nb][1], b[nb][2], b[nb][3], bd);
            }
            #pragma unroll
            for (int mf = 0; mf < 4; mf++) {
                #pragma unroll
                for (int nf = 0; nf < 4; nf++) {
                    int nb = nf >> 1;
                    uint32_t b0 = (nf & 1) ? b[nb][1] : b[nb][0];
                    uint32_t b1 = (nf & 1) ? b[nb][3] : b[nb][2];
                    MMA_BF16(c[mf][nf], a[mf], b0, b1);
                }
            }
        }
        __syncthreads();
    }

    int rq = lane >> 2, cq = (lane & 3) * 2;
    float2 bv[4];
    #pragma unroll
    for (int nf = 0; nf < 4; nf++) {
        int col = n0 + wn * 32 + nf * 8 + cq;
        bv[nf] = make_float2(bias[col], bias[col + 1]);
    }

    #pragma unroll
    for (int mf = 0; mf < 4; mf++) {
        #pragma unroll
        for (int nf = 0; nf < 4; nf++) {
            int r   = m0 + wm * 64 + mf * 16 + rq;
            int col = n0 + wn * 32 + nf * 8 + cq;
            float2 lo = make_float2(c[mf][nf][0] + bv[nf].x, c[mf][nf][1] + bv[nf].y);
            float2 hi = make_float2(c[mf][nf][2] + bv[nf].x, c[mf][nf][3] + bv[nf].y);
            if (mode == 3) {
                *(float2*)(dst_param + (size_t)r * 1024 + col)       = lo;
                *(float2*)(dst_param + (size_t)(r + 8) * 1024 + col) = hi;
            } else {
                float* g = (mode == 0) ? g_Q : (mode == 1) ? g_K : g_V;
                int h = col >> 6, d0 = col & 63;
                int b1 = r >> 11, s1 = r & 2047;
                *(float2*)(g + (((size_t)(b1 * NH + h) * SEQ + s1) << 6) + d0) = lo;
                int s2 = (r + 8) & 2047;
                *(float2*)(g + (((size_t)(b1 * NH + h) * SEQ + s2) << 6) + d0) = hi;
            }
        }
    }
}

// ---------------------------------------------------------------------------
// RoPE (in-place on g_Q / g_K)
// ---------------------------------------------------------------------------
__global__ void rope_kernel()
{
    int gw   = (blockIdx.x * blockDim.x + threadIdx.x) >> 5;
    int lane = threadIdx.x & 31;
    float* base = (blockIdx.y == 0) ? g_Q : g_K;
    int s = gw & (SEQ - 1);
    float* row = base + (size_t)gw * HD;

    float invf = (float)pow(10000.0, -(double)lane / 32.0);
    float sn, cs;
    sincosf((float)s * invf, &sn, &cs);

    float xe   = row[lane];
    float xe32 = row[lane + 32];
    float x2e  = row[2 * lane];
    float x2e1 = row[2 * lane + 1];
    __syncwarp();
    row[lane]      = xe   * cs - x2e1 * sn;
    row[lane + 32] = xe32 * cs + x2e  * sn;
}

// ---------------------------------------------------------------------------
// Flash attention via mma.sync fp16 (hi/lo splits). BM=64, BN=64, 128 thr.
// Warp w owns q rows [q0+16w, q0+16w+16). S and ctx accum in fp32.
// K/V fp32->fp16 hi/lo in smem, pitch 72 halfs (144B, conflict-free ldmatrix).
// P stays in registers (S-accum fragment == A-operand fragment).
// ---------------------------------------------------------------------------
#define AP 72

__global__ __launch_bounds__(128)
void attn_mma()
{
    __shared__ __align__(16) __half Khi[64*AP];
    __shared__ __align__(16) __half Klo[64*AP];
    __shared__ __align__(16) __half Vhi[64*AP];
    __shared__ __align__(16) __half Vlo[64*AP];

    int tid  = threadIdx.x;
    int lane = tid & 31;
    int wid  = tid >> 5;            // 0..3
    int bh   = blockIdx.y;
    int q0   = blockIdx.x << 6;

    const float* Qb = g_Q + (size_t)bh * SEQ * HD;
    const float* Kb = g_K + (size_t)bh * SEQ * HD;
    const float* Vb = g_V + (size_t)bh * SEQ * HD;

    int lr = ((lane >> 3) & 1) * 8 + (lane & 7);
    int lk = (lane >> 4) * 8;
    int rq = lane >> 2, cq = (lane & 3) * 2;

    // ---- stage Q (x0.125, split) into Khi/Klo, ldmatrix into regs ----
    #pragma unroll
    for (int it = 0; it < 8; it++) {
        int id = tid + it * 128;
        int r = id >> 4, c4 = (id & 15) << 2;
        float4 v = *(const float4*)(Qb + ((size_t)(q0 + r) << 6) + c4);
        v.x *= 0.125f; v.y *= 0.125f; v.z *= 0.125f; v.w *= 0.125f;
        __half2 h01 = __floats2half2_rn(v.x, v.y);
        __half2 h23 = __floats2half2_rn(v.z, v.w);
        __half2 l01 = __floats2half2_rn(v.x - __half2float(__low2half(h01)),
                                        v.y - __half2float(__high2half(h01)));
        __half2 l23 = __floats2half2_rn(v.z - __half2float(__low2half(h23)),
                                        v.w - __half2float(__high2half(h23)));
        *(__half2*)&Khi[r*AP + c4]     = h01;
        *(__half2*)&Khi[r*AP + c4 + 2] = h23;
        *(__half2*)&Klo[r*AP + c4]     = l01;
        *(__half2*)&Klo[r*AP + c4 + 2] = l23;
    }
    __syncthreads();

    uint32_t qh[4][4], ql[4][4];
    uint32_t khi_base = smem_u32(Khi), klo_base = smem_u32(Klo);
    uint32_t vhi_base = smem_u32(Vhi), vlo_base = smem_u32(Vlo);
    #pragma unroll
    for (int kc = 0; kc < 4; kc++) {
        uint32_t off = (uint32_t)(wid*16 + lr) * (AP*2) + (kc*16 + lk) * 2;
        LDMATRIX_X4(qh[kc][0], qh[kc][1], qh[kc][2], qh[kc][3], khi_base + off);
        LDMATRIX_X4(ql[kc][0], ql[kc][1], ql[kc][2], ql[kc][3], klo_base + off);
    }
    __syncthreads();

    float acc[8][4];
    #pragma unroll
    for (int nf = 0; nf < 8; nf++)
        #pragma unroll
        for (int v = 0; v < 4; v++) acc[nf][v] = 0.0f;
    float m_i[2] = {-1e30f, -1e30f};
    float l_i[2] = {0.0f, 0.0f};

    int ntiles = blockIdx.x + 1;
    #pragma unroll 1
    for (int t = 0; t < ntiles; t++) {
        int k0 = t << 6;
        // ---- load + convert K,V tile ----
        #pragma unroll
        for (int it = 0; it < 8; it++) {
            int id = tid + it * 128;
            int r = id >> 4, c4 = (id & 15) << 2;
            float4 kv = *(const float4*)(Kb + ((size_t)(k0 + r) << 6) + c4);
            float4 vv = *(const float4*)(Vb + ((size_t)(k0 + r) << 6) + c4);
            __half2 kh01 = __floats2half2_rn(kv.x, kv.y);
            __half2 kh23 = __floats2half2_rn(kv.z, kv.w);
            __half2 kl01 = __floats2half2_rn(kv.x - __half2float(__low2half(kh01)),
                                             kv.y - __half2float(__high2half(kh01)));
            __half2 kl23 = __floats2half2_rn(kv.z - __half2float(__low2half(kh23)),
                                             kv.w - __half2float(__high2half(kh23)));
            *(__half2*)&Khi[r*AP + c4]     = kh01;
            *(__half2*)&Khi[r*AP + c4 + 2] = kh23;
            *(__half2*)&Klo[r*AP + c4]     = kl01;
            *(__half2*)&Klo[r*AP + c4 + 2] = kl23;
            __half2 vh01 = __floats2half2_rn(vv.x, vv.y);
            __half2 vh23 = __floats2half2_rn(vv.z, vv.w);
            __half2 vl01 = __floats2half2_rn(vv.x - __half2float(__low2half(vh01)),
                                             vv.y - __half2float(__high2half(vh01)));
            __half2 vl23 = __floats2half2_rn(vv.z - __half2float(__low2half(vh23)),
                                             vv.w - __half2float(__high2half(vh23)));
            *(__half2*)&Vhi[r*AP + c4]     = vh01;
            *(__half2*)&Vhi[r*AP + c4 + 2] = vh23;
            *(__half2*)&Vlo[r*AP + c4]     = vl01;
            *(__half2*)&Vlo[r*AP + c4 + 2] = vl23;
        }
        __syncthreads();

        // ---- S = Q K^T (3-term split) ----
        float sc[8][4];
        #pragma unroll
        for (int nf = 0; nf < 8; nf++)
            #pragma unroll
            for (int v = 0; v < 4; v++) sc[nf][v] = 0.0f;

        #pragma unroll
        for (int kc = 0; kc < 4; kc++) {
            uint32_t bhf[4][4], blf[4][4];
            #pragma unroll
            for (int nb = 0; nb < 4; nb++) {
                uint32_t off = (uint32_t)(nb*16 + lr) * (AP*2) + (kc*16 + lk) * 2;
                LDMATRIX_X4(bhf[nb][0], bhf[nb][1], bhf[nb][2], bhf[nb][3], khi_base + off);
                LDMATRIX_X4(blf[nb][0], blf[nb][1], blf[nb][2], blf[nb][3], klo_base + off);
            }
            #pragma unroll
            for (int nf = 0; nf < 8; nf++) {
                int nb = nf >> 1;
                uint32_t b0h = (nf & 1) ? bhf[nb][1] : bhf[nb][0];
                uint32_t b1h = (nf & 1) ? bhf[nb][3] : bhf[nb][2];
                uint32_t b0l = (nf & 1) ? blf[nb][1] : blf[nb][0];
                uint32_t b1l = (nf & 1) ? blf[nb][3] : blf[nb][2];
                MMA_F16(sc[nf], qh[kc], b0h, b1h);
                MMA_F16(sc[nf], ql[kc], b0h, b1h);
                MMA_F16(sc[nf], qh[kc], b0l, b1l);
            }
        }

        // ---- causal mask (diagonal tile only) ----
        if (t == (int)blockIdx.x) {
            int row0 = q0 + wid*16 + rq;
            #pragma unroll
            for (int nf = 0; nf < 8; nf++) {
                int col = k0 + nf*8 + cq;
                if (col     > row0)     sc[nf][0] = -1e30f;
                if (col + 1 > row0)     sc[nf][1] = -1e30f;
                if (col     > row0 + 8) sc[nf][2] = -1e30f;
                if (col + 1 > row0 + 8) sc[nf][3] = -1e30f;
            }
        }

        // ---- online softmax (2 rows per thread) ----
        #pragma unroll
        for (int i = 0; i < 2; i++) {
            float mx = -1e30f;
            #pragma unroll
            for (int nf = 0; nf < 8; nf++)
                mx = fmaxf(mx, fmaxf(sc[nf][2*i], sc[nf][2*i+1]));
            mx = fmaxf(mx, __shfl_xor_sync(0xffffffffu, mx, 1));
            mx = fmaxf(mx, __shfl_xor_sync(0xffffffffu, mx, 2));
            float mnew  = fmaxf(m_i[i], mx);
            float scale = __expf(m_i[i] - mnew);
            float ls = 0.0f;
            #pragma unroll
            for (int nf = 0; nf < 8; nf++) {
                float p0 = __expf(sc[nf][2*i]   - mnew);
                float p1 = __expf(sc[nf][2*i+1] - mnew);
                sc[nf][2*i]   = p0;
                sc[nf][2*i+1] = p1;
                ls += p0 + p1;
            }
            ls += __shfl_xor_sync(0xffffffffu, ls, 1);
            ls += __shfl_xor_sync(0xffffffffu, ls, 2);
            l_i[i] = l_i[i] * scale + ls;
            m_i[i] = mnew;
            #pragma unroll
            for (int nf = 0; nf < 8; nf++) {
                acc[nf][2*i]   *= scale;
                acc[nf][2*i+1] *= scale;
            }
        }

        // ---- ctx += P V (3-term split), P from registers ----
        #pragma unroll
        for (int kc = 0; kc < 4; kc++) {
            uint32_t ph[4], pl[4];
            #pragma unroll
            for (int q = 0; q < 4; q++) {
                int nfi = 2*kc + (q >> 1);
                int v0  = (q & 1) ? 2 : 0;
                float p0 = sc[nfi][v0], p1 = sc[nfi][v0+1];
                __half2 h = __floats2half2_rn(p0, p1);
                __half2 l = __floats2half2_rn(p0 - __half2float(__low2half(h)),
                                              p1 - __half2float(__high2half(h)));
                ph[q] = h2u(h); pl[q] = h2u(l);
            }
            uint32_t vhf[4][4], vlf[4][4];
            #pragma unroll
            for (int db = 0; db < 4; db++) {
                uint32_t off = (uint32_t)(kc*16 + (lane & 15)) * (AP*2)
                             + (db*16 + ((lane >> 4) << 3)) * 2;
                LDMATRIX_X4T(vhf[db][0], vhf[db][1], vhf[db][2], vhf[db][3], vhi_base + off);
                LDMATRIX_X4T(vlf[db][0], vlf[db][1], vlf[db][2], vlf[db][3], vlo_base + off);
            }
            #pragma unroll
            for (int nf = 0; nf < 8; nf++) {
                int db = nf >> 1;
                uint32_t b0h = (nf & 1) ? vhf[db][2] : vhf[db][0];
                uint32_t b1h = (nf & 1) ? vhf[db][3] : vhf[db][1];
                uint32_t b0l = (nf & 1) ? vlf[db][2] : vlf[db][0];
                uint32_t b1l = (nf & 1) ? vlf[db][3] : vlf[db][1];
                MMA_F16(acc[nf], ph, b0h, b1h);
                MMA_F16(acc[nf], pl, b0h, b1h);
                MMA_F16(acc[nf], ph, b0l, b1l);
            }
        }
        __syncthreads();
    }

    // ---- epilogue: normalize, scatter into g_ctx [b][s][h*64+d] ----
    int b = bh >> 4, h = bh & 15;
    #pragma unroll
    for (int i = 0; i < 2; i++) {
        float inv = 1.0f / l_i[i];
        int s = q0 + wid*16 + rq + 8*i;
        float* base = g_ctx + ((size_t)(b * SEQ + s) << 10) + (h << 6);
        #pragma unroll
        for (int nf = 0; nf < 8; nf++) {
            *(float2*)(base + nf*8 + cq) =
                make_float2(acc[nf][2*i] * inv, acc[nf][2*i+1] * inv);
        }
    }
}

// ---------------------------------------------------------------------------
extern "C" void kernel_launch(void* const* d_in, const int* in_sizes, int n_in,
                              void* d_out, int out_size)
{
    const float* query = (const float*)d_in[0];
    const float* key   = (const float*)d_in[1];
    const float* value = (const float*)d_in[2];
    const float* w_q = (const float*)d_in[4];
    const float* b_q = (const float*)d_in[5];
    const float* w_k = (const float*)d_in[6];
    const float* b_k = (const float*)d_in[7];
    const float* w_v = (const float*)d_in[8];
    const float* b_v = (const float*)d_in[9];
    const float* w_o = (const float*)d_in[10];
    const float* b_o = (const float*)d_in[11];
    float* out = (float*)d_out;

    static int attr_set = 0;
    if (!attr_set) {
        cudaFuncSetAttribute(gemm_mma, cudaFuncAttributeMaxDynamicSharedMemorySize, GEMM_SMEM);
        attr_set = 1;
    }

    dim3 ggrid(DIM / 128, MROWS / 128);   // (8, 64)

    split_kernel<<<MROWS, 256>>>(query, MROWS, 0);
    split_kernel<<<DIM,   256>>>(w_q,   DIM,   1);
    gemm_mma<<<ggrid, 256, GEMM_SMEM>>>(b_q, nullptr, 0);

    split_kernel<<<MROWS, 256>>>(key, MROWS, 0);
    split_kernel<<<DIM,   256>>>(w_k, DIM,   1);
    gemm_mma<<<ggrid, 256, GEMM_SMEM>>>(b_k, nullptr, 1);

    split_kernel<<<MROWS, 256>>>(value, MROWS, 0);
    split_kernel<<<DIM,   256>>>(w_v,   DIM,   1);
    gemm_mma<<<ggrid, 256, GEMM_SMEM>>>(b_v, nullptr, 2);

    rope_kernel<<<dim3(BATCH*NH*SEQ/8, 2), 256>>>();
    attn_mma<<<dim3(SEQ/64, BATCH*NH), 128>>>();

    split_kernel<<<MROWS, 256>>>(nullptr, MROWS, 0);   // g_ctx
    split_kernel<<<DIM,   256>>>(w_o,     DIM,   1);
    gemm_mma<<<ggrid, 256, GEMM_SMEM>>>(b_o, out, 3);
}

// round 6
// speedup vs baseline: 1.8595x; 1.0112x over previous
#include <cuda_runtime.h>
#include <cuda_bf16.h>
#include <cuda_fp16.h>
#include <math.h>
#include <stdint.h>

#define BATCH 4
#define SEQ   2048
#define DIM   1024
#define NH    16
#define HD    64
#define MROWS (BATCH*SEQ)

// ---------------------------------------------------------------------------
// Scratch (__device__ globals; allocation-free rule)
// ---------------------------------------------------------------------------
__device__ float g_Q[BATCH*NH*SEQ*HD];
__device__ float g_K[BATCH*NH*SEQ*HD];
__device__ float g_V[BATCH*NH*SEQ*HD];
__device__ float g_ctx[(size_t)MROWS*DIM];
__device__ __nv_bfloat16 g_A2[(size_t)MROWS*2048];
__device__ __nv_bfloat16 g_B2[(size_t)DIM*2048];
// fp16 hi/lo planes for attention (RoPE + scale pre-applied to Q/K)
__device__ __half g_Qh[BATCH*NH*SEQ*HD];
__device__ __half g_Ql[BATCH*NH*SEQ*HD];
__device__ __half g_Kh[BATCH*NH*SEQ*HD];
__device__ __half g_Kl[BATCH*NH*SEQ*HD];
__device__ __half g_Vh[BATCH*NH*SEQ*HD];
__device__ __half g_Vl[BATCH*NH*SEQ*HD];

__device__ __forceinline__ uint32_t smem_u32(const void* p) {
    uint32_t a;
    asm("{ .reg .u64 t; cvta.to.shared.u64 t, %1; cvt.u32.u64 %0, t; }" : "=r"(a) : "l"(p));
    return a;
}

#define LDMATRIX_X4(r0, r1, r2, r3, addr) \
    asm volatile("ldmatrix.sync.aligned.m8n8.x4.shared.b16 {%0,%1,%2,%3}, [%4];" \
        : "=r"(r0), "=r"(r1), "=r"(r2), "=r"(r3) : "r"(addr))

#define LDMATRIX_X4T(r0, r1, r2, r3, addr) \
    asm volatile("ldmatrix.sync.aligned.m8n8.x4.trans.shared.b16 {%0,%1,%2,%3}, [%4];" \
        : "=r"(r0), "=r"(r1), "=r"(r2), "=r"(r3) : "r"(addr))

#define MMA_BF16(c, a, b0v, b1v) \
    asm volatile("mma.sync.aligned.m16n8k16.row.col.f32.bf16.bf16.f32 " \
        "{%0,%1,%2,%3}, {%4,%5,%6,%7}, {%8,%9}, {%0,%1,%2,%3};" \
        : "+f"((c)[0]), "+f"((c)[1]), "+f"((c)[2]), "+f"((c)[3]) \
        : "r"((a)[0]), "r"((a)[1]), "r"((a)[2]), "r"((a)[3]), "r"(b0v), "r"(b1v))

#define MMA_F16(c, a, b0v, b1v) \
    asm volatile("mma.sync.aligned.m16n8k16.row.col.f32.f16.f16.f32 " \
        "{%0,%1,%2,%3}, {%4,%5,%6,%7}, {%8,%9}, {%0,%1,%2,%3};" \
        : "+f"((c)[0]), "+f"((c)[1]), "+f"((c)[2]), "+f"((c)[3]) \
        : "r"((a)[0]), "r"((a)[1]), "r"((a)[2]), "r"((a)[3]), "r"(b0v), "r"(b1v))

#define CP_ASYNC16(dst, src) \
    asm volatile("cp.async.cg.shared.global [%0], [%1], 16;" :: "r"(dst), "l"(src))
#define CP_COMMIT() asm volatile("cp.async.commit_group;" ::: "memory")
#define CP_WAIT0()  asm volatile("cp.async.wait_group 0;" ::: "memory")
#define CP_WAIT1()  asm volatile("cp.async.wait_group 1;" ::: "memory")

__device__ __forceinline__ uint32_t h2u(__half2 h) { return *reinterpret_cast<uint32_t*>(&h); }
__device__ __forceinline__ float ex2f(float x) {
    float y; asm("ex2.approx.f32 %0, %1;" : "=f"(y) : "f"(x)); return y;
}

// ---------------------------------------------------------------------------
// f32 -> bf16 hi/lo split (for projection GEMMs)
// ---------------------------------------------------------------------------
struct bf4 { __nv_bfloat162 a, b; };
__global__ void split_kernel(const float* __restrict__ in, int nrows, int which)
{
    const float* src = in ? in : g_ctx;
    int i = blockIdx.x * blockDim.x + threadIdx.x;
    if (i >= nrows * 256) return;
    int r = i >> 8, c4 = i & 255;
    float4 v = ((const float4*)src)[i];
    __nv_bfloat16 h0 = __float2bfloat16(v.x);
    __nv_bfloat16 h1 = __float2bfloat16(v.y);
    __nv_bfloat16 h2 = __float2bfloat16(v.z);
    __nv_bfloat16 h3 = __float2bfloat16(v.w);
    __nv_bfloat16 l0 = __float2bfloat16(v.x - __bfloat162float(h0));
    __nv_bfloat16 l1 = __float2bfloat16(v.y - __bfloat162float(h1));
    __nv_bfloat16 l2 = __float2bfloat16(v.z - __bfloat162float(h2));
    __nv_bfloat16 l3 = __float2bfloat16(v.w - __bfloat162float(h3));
    __nv_bfloat16* out = which ? g_B2 : g_A2;
    size_t base = (size_t)r * 2048 + c4 * 4;
    bf4 hv; hv.a = __nv_bfloat162(h0, h1); hv.b = __nv_bfloat162(h2, h3);
    bf4 lv; lv.a = __nv_bfloat162(l0, l1); lv.b = __nv_bfloat162(l2, l3);
    *(bf4*)(out + base)        = hv;
    *(bf4*)(out + base + 1024) = lv;
}

// ---------------------------------------------------------------------------
// mma.sync bf16x3 GEMM (unchanged, passing)
// ---------------------------------------------------------------------------
#define PITCH    72
#define STAGE_B  (128*PITCH*2)
#define GEMM_SMEM (4*STAGE_B)

__global__ __launch_bounds__(256)
void gemm_mma(const float* __restrict__ bias, float* __restrict__ dst_param, int mode)
{
    extern __shared__ __align__(16) char sm[];
    uint32_t sb = smem_u32(sm);

    int tid  = threadIdx.x;
    int lane = tid & 31;
    int wid  = tid >> 5;
    int wm   = wid & 1;
    int wn   = wid >> 1;
    int m0 = blockIdx.y << 7, n0 = blockIdx.x << 7;

    int lr = ((lane >> 3) & 1) * 8 + (lane & 7);
    int lk = (lane >> 4) * 8;

    float c[4][4][4];
    #pragma unroll
    for (int mf = 0; mf < 4; mf++)
        #pragma unroll
        for (int nf = 0; nf < 4; nf++)
            #pragma unroll
            for (int v = 0; v < 4; v++) c[mf][nf][v] = 0.0f;

    auto load_stage = [&](int t, int buf) {
        int kp = t << 6;
        int ac = kp & 2047;
        int bc = kp - ((kp >= 1024) ? 1024 : 0);
        const __nv_bfloat16* Ab = g_A2 + (size_t)m0 * 2048 + ac;
        const __nv_bfloat16* Bb = g_B2 + (size_t)n0 * 2048 + bc;
        uint32_t sa  = sb + buf * STAGE_B;
        uint32_t sbb = sb + 2 * STAGE_B + buf * STAGE_B;
        #pragma unroll
        for (int it = 0; it < 4; it++) {
            int id = tid + (it << 8);
            int r = id >> 3, ch = id & 7;
            CP_ASYNC16(sa  + r * 144 + (ch << 4), Ab + (size_t)r * 2048 + (ch << 3));
            CP_ASYNC16(sbb + r * 144 + (ch << 4), Bb + (size_t)r * 2048 + (ch << 3));
        }
        CP_COMMIT();
    };

    load_stage(0, 0);

    #pragma unroll 1
    for (int t = 0; t < 48; t++) {
        CP_WAIT0();
        __syncthreads();
        if (t + 1 < 48) load_stage(t + 1, (t + 1) & 1);

        uint32_t sa  = sb + (t & 1) * STAGE_B;
        uint32_t sbb = sb + 2 * STAGE_B + (t & 1) * STAGE_B;

        #pragma unroll
        for (int kk = 0; kk < 64; kk += 16) {
            uint32_t a[4][4];
            #pragma unroll
            for (int mf = 0; mf < 4; mf++) {
                uint32_t ad = sa + (uint32_t)(wm * 64 + mf * 16 + lr) * 144 + (kk + lk) * 2;
                LDMATRIX_X4(a[mf][0], a[mf][1], a[mf][2], a[mf][3], ad);
            }
            uint32_t b[2][4];
            #pragma unroll
            for (int nb = 0; nb < 2; nb++) {
                uint32_t bd = sbb + (uint32_t)(wn * 32 + nb * 16 + lr) * 144 + (kk + lk) * 2;
                LDMATRIX_X4(b[nb][0], b[nb][1], b[nb][2], b[nb][3], bd);
            }
            #pragma unroll
            for (int mf = 0; mf < 4; mf++) {
                #pragma unroll
                for (int nf = 0; nf < 4; nf++) {
                    int nb = nf >> 1;
                    uint32_t b0 = (nf & 1) ? b[nb][1] : b[nb][0];
                    uint32_t b1 = (nf & 1) ? b[nb][3] : b[nb][2];
                    MMA_BF16(c[mf][nf], a[mf], b0, b1);
                }
            }
        }
        __syncthreads();
    }

    int rq = lane >> 2, cq = (lane & 3) * 2;
    float2 bv[4];
    #pragma unroll
    for (int nf = 0; nf < 4; nf++) {
        int col = n0 + wn * 32 + nf * 8 + cq;
        bv[nf] = make_float2(bias[col], bias[col + 1]);
    }

    #pragma unroll
    for (int mf = 0; mf < 4; mf++) {
        #pragma unroll
        for (int nf = 0; nf < 4; nf++) {
            int r   = m0 + wm * 64 + mf * 16 + rq;
            int col = n0 + wn * 32 + nf * 8 + cq;
            float2 lo = make_float2(c[mf][nf][0] + bv[nf].x, c[mf][nf][1] + bv[nf].y);
            float2 hi = make_float2(c[mf][nf][2] + bv[nf].x, c[mf][nf][3] + bv[nf].y);
            if (mode == 3) {
                *(float2*)(dst_param + (size_t)r * 1024 + col)       = lo;
                *(float2*)(dst_param + (size_t)(r + 8) * 1024 + col) = hi;
            } else {
                float* g = (mode == 0) ? g_Q : (mode == 1) ? g_K : g_V;
                int h = col >> 6, d0 = col & 63;
                int b1 = r >> 11, s1 = r & 2047;
                *(float2*)(g + (((size_t)(b1 * NH + h) * SEQ + s1) << 6) + d0) = lo;
                int s2 = (r + 8) & 2047;
                *(float2*)(g + (((size_t)(b1 * NH + h) * SEQ + s2) << 6) + d0) = hi;
            }
        }
    }
}

// ---------------------------------------------------------------------------
// Fused RoPE + fp16 hi/lo conversion.  blockIdx.y: 0=Q (rope+scale), 1=K (rope),
// 2=V (plain). Q scale = 0.125*log2(e) folds the exp2-domain softmax scale.
// ---------------------------------------------------------------------------
#define QSCALE 0.18033688011112042f   // 0.125 * log2(e)

__global__ void conv_rope()
{
    int gw   = (blockIdx.x * blockDim.x + threadIdx.x) >> 5;
    int lane = threadIdx.x & 31;
    int which = blockIdx.y;
    const float* src = (which == 0) ? g_Q : (which == 1) ? g_K : g_V;
    __half* dh = (which == 0) ? g_Qh : (which == 1) ? g_Kh : g_Vh;
    __half* dl = (which == 0) ? g_Ql : (which == 1) ? g_Kl : g_Vl;
    int s = gw & (SEQ - 1);
    const float* row = src + (size_t)gw * HD;

    float v0, v1;
    if (which < 2) {
        float invf = (float)pow(10000.0, -(double)lane / 32.0);
        float sn, cs;
        sincosf((float)s * invf, &sn, &cs);
        float xe   = row[lane];
        float xe32 = row[lane + 32];
        float x2e  = row[2 * lane];
        float x2e1 = row[2 * lane + 1];
        v0 = xe   * cs - x2e1 * sn;
        v1 = xe32 * cs + x2e  * sn;
        if (which == 0) { v0 *= QSCALE; v1 *= QSCALE; }
    } else {
        v0 = row[lane];
        v1 = row[lane + 32];
    }
    __half h0 = __float2half_rn(v0);
    __half h1 = __float2half_rn(v1);
    size_t o = (size_t)gw * HD;
    dh[o + lane]      = h0;
    dh[o + lane + 32] = h1;
    dl[o + lane]      = __float2half_rn(v0 - __half2float(h0));
    dl[o + lane + 32] = __float2half_rn(v1 - __half2float(h1));
}

// ---------------------------------------------------------------------------
// Flash attention: BM=128 (8 warps), BN=64, pre-converted fp16 hi/lo inputs,
// cp.async double-buffered KV, exp2-domain softmax, P(hi)·V(hi+lo).
// Causal guard FIXED: trigger elementwise mask when tile max col exceeds the
// warp's MIN row (was max row — leaked up to 15 future cols for warps 3/7).
// ---------------------------------------------------------------------------
#define AP 72
#define ROWB (AP*2)
#define PLANE (64*ROWB)          // 9216
#define KVSTAGE (4*PLANE)        // 36864
#define ATTN_SMEM (2*KVSTAGE)    // 73728

__global__ __launch_bounds__(256, 2)
void attn_mma()
{
    extern __shared__ __align__(16) char smb[];
    uint32_t sb = smem_u32(smb);

    int tid  = threadIdx.x;
    int lane = tid & 31;
    int wid  = tid >> 5;                    // 0..7
    int bh   = blockIdx.y;
    int bx   = gridDim.x - 1 - blockIdx.x;  // heaviest CTAs first
    int q0   = bx << 7;
    int nt   = 2 * bx + 2;

    const __half* Qh = g_Qh + (size_t)bh * SEQ * HD;
    const __half* Ql = g_Ql + (size_t)bh * SEQ * HD;
    const __half* Kh = g_Kh + (size_t)bh * SEQ * HD;
    const __half* Kl = g_Kl + (size_t)bh * SEQ * HD;
    const __half* Vh = g_Vh + (size_t)bh * SEQ * HD;
    const __half* Vl = g_Vl + (size_t)bh * SEQ * HD;

    int lr = ((lane >> 3) & 1) * 8 + (lane & 7);
    int lk = (lane >> 4) * 8;
    int rq = lane >> 2, cq = (lane & 3) * 2;

    auto load_kv = [&](int t, int stage) {
        int k0 = t << 6;
        uint32_t base = sb + stage * KVSTAGE;
        #pragma unroll
        for (int it = 0; it < 2; it++) {
            int id = tid + (it << 8);
            int r = id >> 3, ch = id & 7;
            uint32_t o = r * ROWB + (ch << 4);
            int go = ((k0 + r) << 6) + (ch << 3);
            CP_ASYNC16(base + o,             Kh + go);
            CP_ASYNC16(base + PLANE + o,     Kl + go);
            CP_ASYNC16(base + 2*PLANE + o,   Vh + go);
            CP_ASYNC16(base + 3*PLANE + o,   Vl + go);
        }
        CP_COMMIT();
    };

    // prologue: Q into stage0 area, KV(0) into stage1
    #pragma unroll
    for (int it = 0; it < 4; it++) {
        int id = tid + (it << 8);
        int r = id >> 3, ch = id & 7;
        uint32_t o = r * ROWB + (ch << 4);
        int go = ((q0 + r) << 6) + (ch << 3);
        CP_ASYNC16(sb + o,             Qh + go);
        CP_ASYNC16(sb + 2*PLANE + o,   Ql + go);
    }
    CP_COMMIT();
    load_kv(0, 1);
    CP_WAIT0();
    __syncthreads();

    uint32_t qh[4][4], ql[4][4];
    #pragma unroll
    for (int kc = 0; kc < 4; kc++) {
        uint32_t off = (uint32_t)(wid*16 + lr) * ROWB + (kc*16 + lk) * 2;
        LDMATRIX_X4(qh[kc][0], qh[kc][1], qh[kc][2], qh[kc][3], sb + off);
        LDMATRIX_X4(ql[kc][0], ql[kc][1], ql[kc][2], ql[kc][3], sb + 2*PLANE + off);
    }
    __syncthreads();   // Q area free for KV(1)

    float acc[8][4];
    #pragma unroll
    for (int nf = 0; nf < 8; nf++)
        #pragma unroll
        for (int v = 0; v < 4; v++) acc[nf][v] = 0.0f;
    float m_i[2] = {-1e30f, -1e30f};
    float l_i[2] = {0.0f, 0.0f};

    int wminrow = q0 + wid*16;   // FIX: guard on the warp's first row

    #pragma unroll 1
    for (int t = 0; t < nt; t++) {
        int k0 = t << 6;
        if (t + 1 < nt) { load_kv(t + 1, t & 1); CP_WAIT1(); }
        else            { CP_WAIT0(); }
        __syncthreads();

        uint32_t khb = sb + ((t + 1) & 1) * KVSTAGE;
        uint32_t klb = khb + PLANE;
        uint32_t vhb = khb + 2*PLANE;
        uint32_t vlb = khb + 3*PLANE;

        // ---- S = Q K^T (3-term hi/lo) ----
        float sc[8][4];
        #pragma unroll
        for (int nf = 0; nf < 8; nf++)
            #pragma unroll
            for (int v = 0; v < 4; v++) sc[nf][v] = 0.0f;

        #pragma unroll
        for (int kc = 0; kc < 4; kc++) {
            #pragma unroll
            for (int nb = 0; nb < 4; nb++) {
                uint32_t off = (uint32_t)(nb*16 + lr) * ROWB + (kc*16 + lk) * 2;
                uint32_t bh0, bh1, bh2, bh3, bl0, bl1, bl2, bl3;
                LDMATRIX_X4(bh0, bh1, bh2, bh3, khb + off);
                LDMATRIX_X4(bl0, bl1, bl2, bl3, klb + off);
                MMA_F16(sc[2*nb],   qh[kc], bh0, bh2);
                MMA_F16(sc[2*nb],   ql[kc], bh0, bh2);
                MMA_F16(sc[2*nb],   qh[kc], bl0, bl2);
                MMA_F16(sc[2*nb+1], qh[kc], bh1, bh3);
                MMA_F16(sc[2*nb+1], ql[kc], bh1, bh3);
                MMA_F16(sc[2*nb+1], qh[kc], bl1, bl3);
            }
        }

        // ---- causal mask (any warp whose rows can see future cols) ----
        if (k0 + 63 > wminrow) {
            int row0 = wminrow + rq;
            #pragma unroll
            for (int nf = 0; nf < 8; nf++) {
                int col = k0 + nf*8 + cq;
                if (col     > row0)     sc[nf][0] = -1e30f;
                if (col + 1 > row0)     sc[nf][1] = -1e30f;
                if (col     > row0 + 8) sc[nf][2] = -1e30f;
                if (col + 1 > row0 + 8) sc[nf][3] = -1e30f;
            }
        }

        // ---- online softmax in exp2 domain (2 rows per thread) ----
        #pragma unroll
        for (int i = 0; i < 2; i++) {
            float mx = -1e30f;
            #pragma unroll
            for (int nf = 0; nf < 8; nf++)
                mx = fmaxf(mx, fmaxf(sc[nf][2*i], sc[nf][2*i+1]));
            mx = fmaxf(mx, __shfl_xor_sync(0xffffffffu, mx, 1));
            mx = fmaxf(mx, __shfl_xor_sync(0xffffffffu, mx, 2));
            float mnew  = fmaxf(m_i[i], mx);
            float scale = ex2f(m_i[i] - mnew);
            float ls = 0.0f;
            #pragma unroll
            for (int nf = 0; nf < 8; nf++) {
                float p0 = ex2f(sc[nf][2*i]   - mnew);
                float p1 = ex2f(sc[nf][2*i+1] - mnew);
                sc[nf][2*i]   = p0;
                sc[nf][2*i+1] = p1;
                ls += p0 + p1;
            }
            ls += __shfl_xor_sync(0xffffffffu, ls, 1);
            ls += __shfl_xor_sync(0xffffffffu, ls, 2);
            l_i[i] = l_i[i] * scale + ls;
            m_i[i] = mnew;
            #pragma unroll
            for (int nf = 0; nf < 8; nf++) {
                acc[nf][2*i]   *= scale;
                acc[nf][2*i+1] *= scale;
            }
        }

        // ---- ctx += P(hi) * (Vhi + Vlo), P from registers ----
        #pragma unroll
        for (int kc = 0; kc < 4; kc++) {
            uint32_t ph[4];
            ph[0] = h2u(__floats2half2_rn(sc[2*kc][0],   sc[2*kc][1]));
            ph[1] = h2u(__floats2half2_rn(sc[2*kc][2],   sc[2*kc][3]));
            ph[2] = h2u(__floats2half2_rn(sc[2*kc+1][0], sc[2*kc+1][1]));
            ph[3] = h2u(__floats2half2_rn(sc[2*kc+1][2], sc[2*kc+1][3]));
            #pragma unroll
            for (int db = 0; db < 4; db++) {
                uint32_t off = (uint32_t)(kc*16 + (lane & 15)) * ROWB
                             + (db*16 + ((lane >> 4) << 3)) * 2;
                uint32_t vh0, vh1, vh2, vh3, vl0, vl1, vl2, vl3;
                LDMATRIX_X4T(vh0, vh1, vh2, vh3, vhb + off);
                LDMATRIX_X4T(vl0, vl1, vl2, vl3, vlb + off);
                MMA_F16(acc[2*db],   ph, vh0, vh1);
                MMA_F16(acc[2*db],   ph, vl0, vl1);
                MMA_F16(acc[2*db+1], ph, vh2, vh3);
                MMA_F16(acc[2*db+1], ph, vl2, vl3);
            }
        }
        __syncthreads();
    }

    // ---- epilogue: normalize, scatter into g_ctx [b][s][h*64+d] ----
    int b = bh >> 4, h = bh & 15;
    #pragma unroll
    for (int i = 0; i < 2; i++) {
        float inv = 1.0f / l_i[i];
        int s = q0 + wid*16 + rq + 8*i;
        float* base = g_ctx + ((size_t)(b * SEQ + s) << 10) + (h << 6);
        #pragma unroll
        for (int nf = 0; nf < 8; nf++) {
            *(float2*)(base + nf*8 + cq) =
                make_float2(acc[nf][2*i] * inv, acc[nf][2*i+1] * inv);
        }
    }
}

// ---------------------------------------------------------------------------
extern "C" void kernel_launch(void* const* d_in, const int* in_sizes, int n_in,
                              void* d_out, int out_size)
{
    const float* query = (const float*)d_in[0];
    const float* key   = (const float*)d_in[1];
    const float* value = (const float*)d_in[2];
    const float* w_q = (const float*)d_in[4];
    const float* b_q = (const float*)d_in[5];
    const float* w_k = (const float*)d_in[6];
    const float* b_k = (const float*)d_in[7];
    const float* w_v = (const float*)d_in[8];
    const float* b_v = (const float*)d_in[9];
    const float* w_o = (const float*)d_in[10];
    const float* b_o = (const float*)d_in[11];
    float* out = (float*)d_out;

    static int attr_set = 0;
    if (!attr_set) {
        cudaFuncSetAttribute(gemm_mma, cudaFuncAttributeMaxDynamicSharedMemorySize, GEMM_SMEM);
        cudaFuncSetAttribute(attn_mma, cudaFuncAttributeMaxDynamicSharedMemorySize, ATTN_SMEM);
        attr_set = 1;
    }

    dim3 ggrid(DIM / 128, MROWS / 128);   // (8, 64)

    split_kernel<<<MROWS, 256>>>(query, MROWS, 0);
    split_kernel<<<DIM,   256>>>(w_q,   DIM,   1);
    gemm_mma<<<ggrid, 256, GEMM_SMEM>>>(b_q, nullptr, 0);

    split_kernel<<<MROWS, 256>>>(key, MROWS, 0);
    split_kernel<<<DIM,   256>>>(w_k, DIM,   1);
    gemm_mma<<<ggrid, 256, GEMM_SMEM>>>(b_k, nullptr, 1);

    split_kernel<<<MROWS, 256>>>(value, MROWS, 0);
    split_kernel<<<DIM,   256>>>(w_v,   DIM,   1);
    gemm_mma<<<ggrid, 256, GEMM_SMEM>>>(b_v, nullptr, 2);

    // fused RoPE + fp16 hi/lo conversion for Q, K, V
    conv_rope<<<dim3(BATCH*NH*SEQ/8, 3), 256>>>();

    attn_mma<<<dim3(SEQ/128, BATCH*NH), 256, ATTN_SMEM>>>();

    split_kernel<<<MROWS, 256>>>(nullptr, MROWS, 0);   // g_ctx
    split_kernel<<<DIM,   256>>>(w_o,     DIM,   1);
    gemm_mma<<<ggrid, 256, GEMM_SMEM>>>(b_o, out, 3);
}

// round 7
// speedup vs baseline: 1.8605x; 1.0005x over previous
#include <cuda_runtime.h>
#include <cuda_bf16.h>
#include <cuda_fp16.h>
#include <math.h>
#include <stdint.h>

#define BATCH 4
#define SEQ   2048
#define DIM   1024
#define NH    16
#define HD    64
#define MROWS (BATCH*SEQ)

// ---------------------------------------------------------------------------
// Scratch (__device__ globals; allocation-free rule)
// ---------------------------------------------------------------------------
__device__ float g_Q[BATCH*NH*SEQ*HD];
__device__ float g_K[BATCH*NH*SEQ*HD];
__device__ float g_V[BATCH*NH*SEQ*HD];
__device__ __nv_bfloat16 g_A2[(size_t)MROWS*2048];
__device__ __nv_bfloat16 g_B2[(size_t)DIM*2048];
// fp16 hi/lo planes for attention (RoPE + scale pre-applied to Q/K)
__device__ __half g_Qh[BATCH*NH*SEQ*HD];
__device__ __half g_Ql[BATCH*NH*SEQ*HD];
__device__ __half g_Kh[BATCH*NH*SEQ*HD];
__device__ __half g_Kl[BATCH*NH*SEQ*HD];
__device__ __half g_Vh[BATCH*NH*SEQ*HD];
__device__ __half g_Vl[BATCH*NH*SEQ*HD];

__device__ __forceinline__ uint32_t smem_u32(const void* p) {
    uint32_t a;
    asm("{ .reg .u64 t; cvta.to.shared.u64 t, %1; cvt.u32.u64 %0, t; }" : "=r"(a) : "l"(p));
    return a;
}

#define LDMATRIX_X4(r0, r1, r2, r3, addr) \
    asm volatile("ldmatrix.sync.aligned.m8n8.x4.shared.b16 {%0,%1,%2,%3}, [%4];" \
        : "=r"(r0), "=r"(r1), "=r"(r2), "=r"(r3) : "r"(addr))

#define LDMATRIX_X4T(r0, r1, r2, r3, addr) \
    asm volatile("ldmatrix.sync.aligned.m8n8.x4.trans.shared.b16 {%0,%1,%2,%3}, [%4];" \
        : "=r"(r0), "=r"(r1), "=r"(r2), "=r"(r3) : "r"(addr))

#define MMA_BF16(c, a, b0v, b1v) \
    asm volatile("mma.sync.aligned.m16n8k16.row.col.f32.bf16.bf16.f32 " \
        "{%0,%1,%2,%3}, {%4,%5,%6,%7}, {%8,%9}, {%0,%1,%2,%3};" \
        : "+f"((c)[0]), "+f"((c)[1]), "+f"((c)[2]), "+f"((c)[3]) \
        : "r"((a)[0]), "r"((a)[1]), "r"((a)[2]), "r"((a)[3]), "r"(b0v), "r"(b1v))

#define MMA_F16(c, a, b0v, b1v) \
    asm volatile("mma.sync.aligned.m16n8k16.row.col.f32.f16.f16.f32 " \
        "{%0,%1,%2,%3}, {%4,%5,%6,%7}, {%8,%9}, {%0,%1,%2,%3};" \
        : "+f"((c)[0]), "+f"((c)[1]), "+f"((c)[2]), "+f"((c)[3]) \
        : "r"((a)[0]), "r"((a)[1]), "r"((a)[2]), "r"((a)[3]), "r"(b0v), "r"(b1v))

#define CP_ASYNC16(dst, src) \
    asm volatile("cp.async.cg.shared.global [%0], [%1], 16;" :: "r"(dst), "l"(src))
#define CP_COMMIT() asm volatile("cp.async.commit_group;" ::: "memory")
#define CP_WAIT0()  asm volatile("cp.async.wait_group 0;" ::: "memory")
#define CP_WAIT1()  asm volatile("cp.async.wait_group 1;" ::: "memory")

__device__ __forceinline__ uint32_t h2u(__half2 h) { return *reinterpret_cast<uint32_t*>(&h); }
__device__ __forceinline__ float ex2f(float x) {
    float y; asm("ex2.approx.f32 %0, %1;" : "=f"(y) : "f"(x)); return y;
}

// ---------------------------------------------------------------------------
// f32 -> bf16 hi/lo split (inputs / weights for projection GEMMs)
// ---------------------------------------------------------------------------
struct bf4 { __nv_bfloat162 a, b; };
__global__ void split_kernel(const float* __restrict__ in, int nrows, int which)
{
    const float* src = in;
    int i = blockIdx.x * blockDim.x + threadIdx.x;
    if (i >= nrows * 256) return;
    int r = i >> 8, c4 = i & 255;
    float4 v = ((const float4*)src)[i];
    __nv_bfloat16 h0 = __float2bfloat16(v.x);
    __nv_bfloat16 h1 = __float2bfloat16(v.y);
    __nv_bfloat16 h2 = __float2bfloat16(v.z);
    __nv_bfloat16 h3 = __float2bfloat16(v.w);
    __nv_bfloat16 l0 = __float2bfloat16(v.x - __bfloat162float(h0));
    __nv_bfloat16 l1 = __float2bfloat16(v.y - __bfloat162float(h1));
    __nv_bfloat16 l2 = __float2bfloat16(v.z - __bfloat162float(h2));
    __nv_bfloat16 l3 = __float2bfloat16(v.w - __bfloat162float(h3));
    __nv_bfloat16* out = which ? g_B2 : g_A2;
    size_t base = (size_t)r * 2048 + c4 * 4;
    bf4 hv; hv.a = __nv_bfloat162(h0, h1); hv.b = __nv_bfloat162(h2, h3);
    bf4 lv; lv.a = __nv_bfloat162(l0, l1); lv.b = __nv_bfloat162(l2, l3);
    *(bf4*)(out + base)        = hv;
    *(bf4*)(out + base + 1024) = lv;
}

// ---------------------------------------------------------------------------
// mma.sync bf16x3 GEMM (unchanged, passing)
// ---------------------------------------------------------------------------
#define PITCH    72
#define STAGE_B  (128*PITCH*2)
#define GEMM_SMEM (4*STAGE_B)

__global__ __launch_bounds__(256)
void gemm_mma(const float* __restrict__ bias, float* __restrict__ dst_param, int mode)
{
    extern __shared__ __align__(16) char sm[];
    uint32_t sb = smem_u32(sm);

    int tid  = threadIdx.x;
    int lane = tid & 31;
    int wid  = tid >> 5;
    int wm   = wid & 1;
    int wn   = wid >> 1;
    int m0 = blockIdx.y << 7, n0 = blockIdx.x << 7;

    int lr = ((lane >> 3) & 1) * 8 + (lane & 7);
    int lk = (lane >> 4) * 8;

    float c[4][4][4];
    #pragma unroll
    for (int mf = 0; mf < 4; mf++)
        #pragma unroll
        for (int nf = 0; nf < 4; nf++)
            #pragma unroll
            for (int v = 0; v < 4; v++) c[mf][nf][v] = 0.0f;

    auto load_stage = [&](int t, int buf) {
        int kp = t << 6;
        int ac = kp & 2047;
        int bc = kp - ((kp >= 1024) ? 1024 : 0);
        const __nv_bfloat16* Ab = g_A2 + (size_t)m0 * 2048 + ac;
        const __nv_bfloat16* Bb = g_B2 + (size_t)n0 * 2048 + bc;
        uint32_t sa  = sb + buf * STAGE_B;
        uint32_t sbb = sb + 2 * STAGE_B + buf * STAGE_B;
        #pragma unroll
        for (int it = 0; it < 4; it++) {
            int id = tid + (it << 8);
            int r = id >> 3, ch = id & 7;
            CP_ASYNC16(sa  + r * 144 + (ch << 4), Ab + (size_t)r * 2048 + (ch << 3));
            CP_ASYNC16(sbb + r * 144 + (ch << 4), Bb + (size_t)r * 2048 + (ch << 3));
        }
        CP_COMMIT();
    };

    load_stage(0, 0);

    #pragma unroll 1
    for (int t = 0; t < 48; t++) {
        CP_WAIT0();
        __syncthreads();
        if (t + 1 < 48) load_stage(t + 1, (t + 1) & 1);

        uint32_t sa  = sb + (t & 1) * STAGE_B;
        uint32_t sbb = sb + 2 * STAGE_B + (t & 1) * STAGE_B;

        #pragma unroll
        for (int kk = 0; kk < 64; kk += 16) {
            uint32_t a[4][4];
            #pragma unroll
            for (int mf = 0; mf < 4; mf++) {
                uint32_t ad = sa + (uint32_t)(wm * 64 + mf * 16 + lr) * 144 + (kk + lk) * 2;
                LDMATRIX_X4(a[mf][0], a[mf][1], a[mf][2], a[mf][3], ad);
            }
            uint32_t b[2][4];
            #pragma unroll
            for (int nb = 0; nb < 2; nb++) {
                uint32_t bd = sbb + (uint32_t)(wn * 32 + nb * 16 + lr) * 144 + (kk + lk) * 2;
                LDMATRIX_X4(b[nb][0], b[nb][1], b[nb][2], b[nb][3], bd);
            }
            #pragma unroll
            for (int mf = 0; mf < 4; mf++) {
                #pragma unroll
                for (int nf = 0; nf < 4; nf++) {
                    int nb = nf >> 1;
                    uint32_t b0 = (nf & 1) ? b[nb][1] : b[nb][0];
                    uint32_t b1 = (nf & 1) ? b[nb][3] : b[nb][2];
                    MMA_BF16(c[mf][nf], a[mf], b0, b1);
                }
            }
        }
        __syncthreads();
    }

    int rq = lane >> 2, cq = (lane & 3) * 2;
    float2 bv[4];
    #pragma unroll
    for (int nf = 0; nf < 4; nf++) {
        int col = n0 + wn * 32 + nf * 8 + cq;
        bv[nf] = make_float2(bias[col], bias[col + 1]);
    }

    #pragma unroll
    for (int mf = 0; mf < 4; mf++) {
        #pragma unroll
        for (int nf = 0; nf < 4; nf++) {
            int r   = m0 + wm * 64 + mf * 16 + rq;
            int col = n0 + wn * 32 + nf * 8 + cq;
            float2 lo = make_float2(c[mf][nf][0] + bv[nf].x, c[mf][nf][1] + bv[nf].y);
            float2 hi = make_float2(c[mf][nf][2] + bv[nf].x, c[mf][nf][3] + bv[nf].y);
            if (mode == 3) {
                *(float2*)(dst_param + (size_t)r * 1024 + col)       = lo;
                *(float2*)(dst_param + (size_t)(r + 8) * 1024 + col) = hi;
            } else {
                float* g = (mode == 0) ? g_Q : (mode == 1) ? g_K : g_V;
                int h = col >> 6, d0 = col & 63;
                int b1 = r >> 11, s1 = r & 2047;
                *(float2*)(g + (((size_t)(b1 * NH + h) * SEQ + s1) << 6) + d0) = lo;
                int s2 = (r + 8) & 2047;
                *(float2*)(g + (((size_t)(b1 * NH + h) * SEQ + s2) << 6) + d0) = hi;
            }
        }
    }
}

// ---------------------------------------------------------------------------
// Fused RoPE + fp16 hi/lo conversion.  blockIdx.y: 0=Q (rope+scale), 1=K (rope),
// 2=V (plain). Q scale = 0.125*log2(e) folds the exp2-domain softmax scale.
// ---------------------------------------------------------------------------
#define QSCALE 0.18033688011112042f   // 0.125 * log2(e)

__global__ void conv_rope()
{
    int gw   = (blockIdx.x * blockDim.x + threadIdx.x) >> 5;
    int lane = threadIdx.x & 31;
    int which = blockIdx.y;
    const float* src = (which == 0) ? g_Q : (which == 1) ? g_K : g_V;
    __half* dh = (which == 0) ? g_Qh : (which == 1) ? g_Kh : g_Vh;
    __half* dl = (which == 0) ? g_Ql : (which == 1) ? g_Kl : g_Vl;
    int s = gw & (SEQ - 1);
    const float* row = src + (size_t)gw * HD;

    float v0, v1;
    if (which < 2) {
        float invf = (float)pow(10000.0, -(double)lane / 32.0);
        float sn, cs;
        sincosf((float)s * invf, &sn, &cs);
        float xe   = row[lane];
        float xe32 = row[lane + 32];
        float x2e  = row[2 * lane];
        float x2e1 = row[2 * lane + 1];
        v0 = xe   * cs - x2e1 * sn;
        v1 = xe32 * cs + x2e  * sn;
        if (which == 0) { v0 *= QSCALE; v1 *= QSCALE; }
    } else {
        v0 = row[lane];
        v1 = row[lane + 32];
    }
    __half h0 = __float2half_rn(v0);
    __half h1 = __float2half_rn(v1);
    size_t o = (size_t)gw * HD;
    dh[o + lane]      = h0;
    dh[o + lane + 32] = h1;
    dl[o + lane]      = __float2half_rn(v0 - __half2float(h0));
    dl[o + lane + 32] = __float2half_rn(v1 - __half2float(h1));
}

// ---------------------------------------------------------------------------
// Flash attention: BM=128 (8 warps), BN=64, pre-converted fp16 hi/lo inputs,
// cp.async double-buffered KV, exp2-domain softmax, P(hi)·V(hi+lo).
// R7: launch_bounds(256) only — no min-blocks clamp (R6's (256,2) forced a
// 128-reg cap and spilled ~20 regs into the hot loop). Epilogue now emits
// bf16 hi/lo straight into g_A2 (fuses the ctx split kernel).
// ---------------------------------------------------------------------------
#define AP 72
#define ROWB (AP*2)
#define PLANE (64*ROWB)          // 9216
#define KVSTAGE (4*PLANE)        // 36864
#define ATTN_SMEM (2*KVSTAGE)    // 73728

__global__ __launch_bounds__(256)
void attn_mma()
{
    extern __shared__ __align__(16) char smb[];
    uint32_t sb = smem_u32(smb);

    int tid  = threadIdx.x;
    int lane = tid & 31;
    int wid  = tid >> 5;                    // 0..7
    int bh   = blockIdx.y;
    int bx   = gridDim.x - 1 - blockIdx.x;  // heaviest CTAs first
    int q0   = bx << 7;
    int nt   = 2 * bx + 2;

    const __half* Qh = g_Qh + (size_t)bh * SEQ * HD;
    const __half* Ql = g_Ql + (size_t)bh * SEQ * HD;
    const __half* Kh = g_Kh + (size_t)bh * SEQ * HD;
    const __half* Kl = g_Kl + (size_t)bh * SEQ * HD;
    const __half* Vh = g_Vh + (size_t)bh * SEQ * HD;
    const __half* Vl = g_Vl + (size_t)bh * SEQ * HD;

    int lr = ((lane >> 3) & 1) * 8 + (lane & 7);
    int lk = (lane >> 4) * 8;
    int rq = lane >> 2, cq = (lane & 3) * 2;

    auto load_kv = [&](int t, int stage) {
        int k0 = t << 6;
        uint32_t base = sb + stage * KVSTAGE;
        #pragma unroll
        for (int it = 0; it < 2; it++) {
            int id = tid + (it << 8);
            int r = id >> 3, ch = id & 7;
            uint32_t o = r * ROWB + (ch << 4);
            int go = ((k0 + r) << 6) + (ch << 3);
            CP_ASYNC16(base + o,             Kh + go);
            CP_ASYNC16(base + PLANE + o,     Kl + go);
            CP_ASYNC16(base + 2*PLANE + o,   Vh + go);
            CP_ASYNC16(base + 3*PLANE + o,   Vl + go);
        }
        CP_COMMIT();
    };

    // prologue: Q into stage0 area, KV(0) into stage1
    #pragma unroll
    for (int it = 0; it < 4; it++) {
        int id = tid + (it << 8);
        int r = id >> 3, ch = id & 7;
        uint32_t o = r * ROWB + (ch << 4);
        int go = ((q0 + r) << 6) + (ch << 3);
        CP_ASYNC16(sb + o,             Qh + go);
        CP_ASYNC16(sb + 2*PLANE + o,   Ql + go);
    }
    CP_COMMIT();
    load_kv(0, 1);
    CP_WAIT0();
    __syncthreads();

    uint32_t qh[4][4], ql[4][4];
    #pragma unroll
    for (int kc = 0; kc < 4; kc++) {
        uint32_t off = (uint32_t)(wid*16 + lr) * ROWB + (kc*16 + lk) * 2;
        LDMATRIX_X4(qh[kc][0], qh[kc][1], qh[kc][2], qh[kc][3], sb + off);
        LDMATRIX_X4(ql[kc][0], ql[kc][1], ql[kc][2], ql[kc][3], sb + 2*PLANE + off);
    }
    __syncthreads();   // Q area free for KV(1)

    float acc[8][4];
    #pragma unroll
    for (int nf = 0; nf < 8; nf++)
        #pragma unroll
        for (int v = 0; v < 4; v++) acc[nf][v] = 0.0f;
    float m_i[2] = {-1e30f, -1e30f};
    float l_i[2] = {0.0f, 0.0f};

    int wminrow = q0 + wid*16;

    #pragma unroll 1
    for (int t = 0; t < nt; t++) {
        int k0 = t << 6;
        if (t + 1 < nt) { load_kv(t + 1, t & 1); CP_WAIT1(); }
        else            { CP_WAIT0(); }
        __syncthreads();

        uint32_t khb = sb + ((t + 1) & 1) * KVSTAGE;
        uint32_t klb = khb + PLANE;
        uint32_t vhb = khb + 2*PLANE;
        uint32_t vlb = khb + 3*PLANE;

        // ---- S = Q K^T (3-term hi/lo) ----
        float sc[8][4];
        #pragma unroll
        for (int nf = 0; nf < 8; nf++)
            #pragma unroll
            for (int v = 0; v < 4; v++) sc[nf][v] = 0.0f;

        #pragma unroll
        for (int kc = 0; kc < 4; kc++) {
            #pragma unroll
            for (int nb = 0; nb < 4; nb++) {
                uint32_t off = (uint32_t)(nb*16 + lr) * ROWB + (kc*16 + lk) * 2;
                uint32_t bh0, bh1, bh2, bh3, bl0, bl1, bl2, bl3;
                LDMATRIX_X4(bh0, bh1, bh2, bh3, khb + off);
                LDMATRIX_X4(bl0, bl1, bl2, bl3, klb + off);
                MMA_F16(sc[2*nb],   qh[kc], bh0, bh2);
                MMA_F16(sc[2*nb],   ql[kc], bh0, bh2);
                MMA_F16(sc[2*nb],   qh[kc], bl0, bl2);
                MMA_F16(sc[2*nb+1], qh[kc], bh1, bh3);
                MMA_F16(sc[2*nb+1], ql[kc], bh1, bh3);
                MMA_F16(sc[2*nb+1], qh[kc], bl1, bl3);
            }
        }

        // ---- causal mask (any warp whose rows can see future cols) ----
        if (k0 + 63 > wminrow) {
            int row0 = wminrow + rq;
            #pragma unroll
            for (int nf = 0; nf < 8; nf++) {
                int col = k0 + nf*8 + cq;
                if (col     > row0)     sc[nf][0] = -1e30f;
                if (col + 1 > row0)     sc[nf][1] = -1e30f;
                if (col     > row0 + 8) sc[nf][2] = -1e30f;
                if (col + 1 > row0 + 8) sc[nf][3] = -1e30f;
            }
        }

        // ---- online softmax in exp2 domain (2 rows per thread) ----
        #pragma unroll
        for (int i = 0; i < 2; i++) {
            float mx = -1e30f;
            #pragma unroll
            for (int nf = 0; nf < 8; nf++)
                mx = fmaxf(mx, fmaxf(sc[nf][2*i], sc[nf][2*i+1]));
            mx = fmaxf(mx, __shfl_xor_sync(0xffffffffu, mx, 1));
            mx = fmaxf(mx, __shfl_xor_sync(0xffffffffu, mx, 2));
            float mnew  = fmaxf(m_i[i], mx);
            float scale = ex2f(m_i[i] - mnew);
            float ls = 0.0f;
            #pragma unroll
            for (int nf = 0; nf < 8; nf++) {
                float p0 = ex2f(sc[nf][2*i]   - mnew);
                float p1 = ex2f(sc[nf][2*i+1] - mnew);
                sc[nf][2*i]   = p0;
                sc[nf][2*i+1] = p1;
                ls += p0 + p1;
            }
            ls += __shfl_xor_sync(0xffffffffu, ls, 1);
            ls += __shfl_xor_sync(0xffffffffu, ls, 2);
            l_i[i] = l_i[i] * scale + ls;
            m_i[i] = mnew;
            #pragma unroll
            for (int nf = 0; nf < 8; nf++) {
                acc[nf][2*i]   *= scale;
                acc[nf][2*i+1] *= scale;
            }
        }

        // ---- ctx += P(hi) * (Vhi + Vlo), P from registers ----
        #pragma unroll
        for (int kc = 0; kc < 4; kc++) {
            uint32_t ph[4];
            ph[0] = h2u(__floats2half2_rn(sc[2*kc][0],   sc[2*kc][1]));
            ph[1] = h2u(__floats2half2_rn(sc[2*kc][2],   sc[2*kc][3]));
            ph[2] = h2u(__floats2half2_rn(sc[2*kc+1][0], sc[2*kc+1][1]));
            ph[3] = h2u(__floats2half2_rn(sc[2*kc+1][2], sc[2*kc+1][3]));
            #pragma unroll
            for (int db = 0; db < 4; db++) {
                uint32_t off = (uint32_t)(kc*16 + (lane & 15)) * ROWB
                             + (db*16 + ((lane >> 4) << 3)) * 2;
                uint32_t vh0, vh1, vh2, vh3, vl0, vl1, vl2, vl3;
                LDMATRIX_X4T(vh0, vh1, vh2, vh3, vhb + off);
                LDMATRIX_X4T(vl0, vl1, vl2, vl3, vlb + off);
                MMA_F16(acc[2*db],   ph, vh0, vh1);
                MMA_F16(acc[2*db],   ph, vl0, vl1);
                MMA_F16(acc[2*db+1], ph, vh2, vh3);
                MMA_F16(acc[2*db+1], ph, vl2, vl3);
            }
        }
        __syncthreads();
    }

    // ---- epilogue: normalize + bf16 hi/lo split straight into g_A2 ----
    // g_A2 row = b*SEQ+s (width 2048: [hi(1024) | lo(1024)]), col = h*64+d.
    int b = bh >> 4, h = bh & 15;
    #pragma unroll
    for (int i = 0; i < 2; i++) {
        float inv = 1.0f / l_i[i];
        int s = q0 + wid*16 + rq + 8*i;
        __nv_bfloat16* rowp = g_A2 + ((size_t)(b * SEQ + s) << 11) + (h << 6);
        #pragma unroll
        for (int nf = 0; nf < 8; nf++) {
            float v0 = acc[nf][2*i]   * inv;
            float v1 = acc[nf][2*i+1] * inv;
            __nv_bfloat16 h0 = __float2bfloat16(v0);
            __nv_bfloat16 h1 = __float2bfloat16(v1);
            __nv_bfloat16 l0 = __float2bfloat16(v0 - __bfloat162float(h0));
            __nv_bfloat16 l1 = __float2bfloat16(v1 - __bfloat162float(h1));
            *(__nv_bfloat162*)(rowp + nf*8 + cq)        = __nv_bfloat162(h0, h1);
            *(__nv_bfloat162*)(rowp + 1024 + nf*8 + cq) = __nv_bfloat162(l0, l1);
        }
    }
}

// ---------------------------------------------------------------------------
extern "C" void kernel_launch(void* const* d_in, const int* in_sizes, int n_in,
                              void* d_out, int out_size)
{
    const float* query = (const float*)d_in[0];
    const float* key   = (const float*)d_in[1];
    const float* value = (const float*)d_in[2];
    const float* w_q = (const float*)d_in[4];
    const float* b_q = (const float*)d_in[5];
    const float* w_k = (const float*)d_in[6];
    const float* b_k = (const float*)d_in[7];
    const float* w_v = (const float*)d_in[8];
    const float* b_v = (const float*)d_in[9];
    const float* w_o = (const float*)d_in[10];
    const float* b_o = (const float*)d_in[11];
    float* out = (float*)d_out;

    static int attr_set = 0;
    if (!attr_set) {
        cudaFuncSetAttribute(gemm_mma, cudaFuncAttributeMaxDynamicSharedMemorySize, GEMM_SMEM);
        cudaFuncSetAttribute(attn_mma, cudaFuncAttributeMaxDynamicSharedMemorySize, ATTN_SMEM);
        attr_set = 1;
    }

    dim3 ggrid(DIM / 128, MROWS / 128);   // (8, 64)

    split_kernel<<<MROWS, 256>>>(query, MROWS, 0);
    split_kernel<<<DIM,   256>>>(w_q,   DIM,   1);
    gemm_mma<<<ggrid, 256, GEMM_SMEM>>>(b_q, nullptr, 0);

    split_kernel<<<MROWS, 256>>>(key, MROWS, 0);
    split_kernel<<<DIM,   256>>>(w_k, DIM,   1);
    gemm_mma<<<ggrid, 256, GEMM_SMEM>>>(b_k, nullptr, 1);

    split_kernel<<<MROWS, 256>>>(value, MROWS, 0);
    split_kernel<<<DIM,   256>>>(w_v,   DIM,   1);
    gemm_mma<<<ggrid, 256, GEMM_SMEM>>>(b_v, nullptr, 2);

    // fused RoPE + fp16 hi/lo conversion for Q, K, V
    conv_rope<<<dim3(BATCH*NH*SEQ/8, 3), 256>>>();

    // attention writes bf16 hi/lo ctx directly into g_A2
    attn_mma<<<dim3(SEQ/128, BATCH*NH), 256, ATTN_SMEM>>>();

    split_kernel<<<DIM, 256>>>(w_o, DIM, 1);
    gemm_mma<<<ggrid, 256, GEMM_SMEM>>>(b_o, out, 3);
}

// round 9
// speedup vs baseline: 1.9550x; 1.0508x over previous
#include <cuda_runtime.h>
#include <cuda_fp16.h>
#include <math.h>
#include <stdint.h>

#define BATCH 4
#define SEQ   2048
#define DIM   1024
#define NH    16
#define HD    64
#define MROWS (BATCH*SEQ)

// ---------------------------------------------------------------------------
// Scratch (__device__ globals; allocation-free rule)
// ---------------------------------------------------------------------------
__device__ float g_Q[BATCH*NH*SEQ*HD];
__device__ float g_K[BATCH*NH*SEQ*HD];
__device__ float g_V[BATCH*NH*SEQ*HD];
// fp16x2 GEMM operands: A2 = [Xhi | Xlo] (row width 2048), B = fp16 weights
__device__ __half g_A2[(size_t)MROWS*2048];
__device__ __half g_B2[(size_t)DIM*DIM];
__device__ __half g_B2o[(size_t)DIM*DIM];
// fp16 hi/lo planes for attention (RoPE + scale pre-applied to Q/K)
__device__ __half g_Qh[BATCH*NH*SEQ*HD];
__device__ __half g_Ql[BATCH*NH*SEQ*HD];
__device__ __half g_Kh[BATCH*NH*SEQ*HD];
__device__ __half g_Kl[BATCH*NH*SEQ*HD];
__device__ __half g_Vh[BATCH*NH*SEQ*HD];
__device__ __half g_Vl[BATCH*NH*SEQ*HD];

__device__ __forceinline__ uint32_t smem_u32(const void* p) {
    uint32_t a;
    asm("{ .reg .u64 t; cvta.to.shared.u64 t, %1; cvt.u32.u64 %0, t; }" : "=r"(a) : "l"(p));
    return a;
}

#define LDMATRIX_X4(r0, r1, r2, r3, addr) \
    asm volatile("ldmatrix.sync.aligned.m8n8.x4.shared.b16 {%0,%1,%2,%3}, [%4];" \
        : "=r"(r0), "=r"(r1), "=r"(r2), "=r"(r3) : "r"(addr))

#define LDMATRIX_X4T(r0, r1, r2, r3, addr) \
    asm volatile("ldmatrix.sync.aligned.m8n8.x4.trans.shared.b16 {%0,%1,%2,%3}, [%4];" \
        : "=r"(r0), "=r"(r1), "=r"(r2), "=r"(r3) : "r"(addr))

#define MMA_F16(c, a, b0v, b1v) \
    asm volatile("mma.sync.aligned.m16n8k16.row.col.f32.f16.f16.f32 " \
        "{%0,%1,%2,%3}, {%4,%5,%6,%7}, {%8,%9}, {%0,%1,%2,%3};" \
        : "+f"((c)[0]), "+f"((c)[1]), "+f"((c)[2]), "+f"((c)[3]) \
        : "r"((a)[0]), "r"((a)[1]), "r"((a)[2]), "r"((a)[3]), "r"(b0v), "r"(b1v))

#define CP_ASYNC16(dst, src) \
    asm volatile("cp.async.cg.shared.global [%0], [%1], 16;" :: "r"(dst), "l"(src))
#define CP_COMMIT() asm volatile("cp.async.commit_group;" ::: "memory")
#define CP_WAIT0()  asm volatile("cp.async.wait_group 0;" ::: "memory")
#define CP_WAIT1()  asm volatile("cp.async.wait_group 1;" ::: "memory")

__device__ __forceinline__ uint32_t h2u(__half2 h) { return *reinterpret_cast<uint32_t*>(&h); }
__device__ __forceinline__ float ex2f(float x) {
    float y; asm("ex2.approx.f32 %0, %1;" : "=f"(y) : "f"(x)); return y;
}

struct h4 { __half2 a, b; };

// ---------------------------------------------------------------------------
// X split: f32 -> fp16 hi/lo into g_A2 (row 2048: [hi(1024) | lo(1024)])
// ---------------------------------------------------------------------------
__global__ void split_x(const float* __restrict__ in)
{
    int i = blockIdx.x * blockDim.x + threadIdx.x;   // float4 index
    if (i >= MROWS * 256) return;
    int r = i >> 8, c4 = i & 255;
    float4 v = ((const float4*)in)[i];
    __half2 h01 = __floats2half2_rn(v.x, v.y);
    __half2 h23 = __floats2half2_rn(v.z, v.w);
    __half2 l01 = __floats2half2_rn(v.x - __half2float(__low2half(h01)),
                                    v.y - __half2float(__high2half(h01)));
    __half2 l23 = __floats2half2_rn(v.z - __half2float(__low2half(h23)),
                                    v.w - __half2float(__high2half(h23)));
    size_t base = (size_t)r * 2048 + c4 * 4;
    h4 hv; hv.a = h01; hv.b = h23;
    h4 lv; lv.a = l01; lv.b = l23;
    *(h4*)(g_A2 + base)        = hv;
    *(h4*)(g_A2 + base + 1024) = lv;
}

// ---------------------------------------------------------------------------
// W convert: f32 -> fp16 (row 1024). which: 0 -> g_B2, 1 -> g_B2o
// ---------------------------------------------------------------------------
__global__ void split_w(const float* __restrict__ in, int which)
{
    int i = blockIdx.x * blockDim.x + threadIdx.x;   // float4 index
    if (i >= DIM * 256) return;
    float4 v = ((const float4*)in)[i];
    h4 hv;
    hv.a = __floats2half2_rn(v.x, v.y);
    hv.b = __floats2half2_rn(v.z, v.w);
    __half* out = which ? g_B2o : g_B2;
    *(h4*)(out + (size_t)i * 4) = hv;
}

// ---------------------------------------------------------------------------
// mma.sync fp16x2 GEMM: C[8192x1024] = (Xhi+Xlo) @ W^T + bias over K'=2048
//   segments: t in [0,16): Xhi*W ; t in [16,32): Xlo*W
// CTA 128x128, 8 warps (2m x 4n), warp tile 64x32, m16n8k16 HMMA.
// BK=64, cp.async double buffered. Pitch 72 halfs (144B) -> conflict-free.
// mode 0/1/2 -> head-major g_Q/g_K/g_V;  mode 3 -> row-major dst_param.
// bsel: 0 -> g_B2, 1 -> g_B2o (resolved device-side; host cannot pass
// __device__ symbol addresses -- that was the R8 bug).
// ---------------------------------------------------------------------------
#define NST      32
#define STAGE_B  (128*144)
#define GEMM_SMEM (4*STAGE_B)            // 73728

__global__ __launch_bounds__(256)
void gemm_mma(const float* __restrict__ bias, float* __restrict__ dst_param,
              int mode, int bsel)
{
    extern __shared__ __align__(16) char sm[];
    uint32_t sb = smem_u32(sm);

    const __half* Bmat = bsel ? g_B2o : g_B2;

    int tid  = threadIdx.x;
    int lane = tid & 31;
    int wid  = tid >> 5;
    int wm   = wid & 1;
    int wn   = wid >> 1;
    int m0 = blockIdx.y << 7, n0 = blockIdx.x << 7;

    int lr = ((lane >> 3) & 1) * 8 + (lane & 7);
    int lk = (lane >> 4) * 8;

    float c[4][4][4];
    #pragma unroll
    for (int mf = 0; mf < 4; mf++)
        #pragma unroll
        for (int nf = 0; nf < 4; nf++)
            #pragma unroll
            for (int v = 0; v < 4; v++) c[mf][nf][v] = 0.0f;

    auto load_stage = [&](int t, int buf) {
        int kp = t << 6;                  // A col in [0,2048)
        int bc = kp & 1023;               // B col in [0,1024)
        const __half* Ab = g_A2 + (size_t)m0 * 2048 + kp;
        const __half* Bb = Bmat + (size_t)n0 * 1024 + bc;
        uint32_t sa  = sb + buf * STAGE_B;
        uint32_t sbb = sb + 2 * STAGE_B + buf * STAGE_B;
        #pragma unroll
        for (int it = 0; it < 4; it++) {
            int id = tid + (it << 8);
            int r = id >> 3, ch = id & 7;
            CP_ASYNC16(sa  + r * 144 + (ch << 4), Ab + (size_t)r * 2048 + (ch << 3));
            CP_ASYNC16(sbb + r * 144 + (ch << 4), Bb + (size_t)r * 1024 + (ch << 3));
        }
        CP_COMMIT();
    };

    load_stage(0, 0);

    #pragma unroll 1
    for (int t = 0; t < NST; t++) {
        CP_WAIT0();
        __syncthreads();
        if (t + 1 < NST) load_stage(t + 1, (t + 1) & 1);

        uint32_t sa  = sb + (t & 1) * STAGE_B;
        uint32_t sbb = sb + 2 * STAGE_B + (t & 1) * STAGE_B;

        #pragma unroll
        for (int kk = 0; kk < 64; kk += 16) {
            uint32_t a[4][4];
            #pragma unroll
            for (int mf = 0; mf < 4; mf++) {
                uint32_t ad = sa + (uint32_t)(wm * 64 + mf * 16 + lr) * 144 + (kk + lk) * 2;
                LDMATRIX_X4(a[mf][0], a[mf][1], a[mf][2], a[mf][3], ad);
            }
            uint32_t b[2][4];
            #pragma unroll
            for (int nb = 0; nb < 2; nb++) {
                uint32_t bd = sbb + (uint32_t)(wn * 32 + nb * 16 + lr) * 144 + (kk + lk) * 2;
                LDMATRIX_X4(b[nb][0], b[nb][1], b[nb][2], b[nb][3], bd);
            }
            #pragma unroll
            for (int mf = 0; mf < 4; mf++) {
                #pragma unroll
                for (int nf = 0; nf < 4; nf++) {
                    int nb = nf >> 1;
                    uint32_t b0 = (nf & 1) ? b[nb][1] : b[nb][0];
                    uint32_t b1 = (nf & 1) ? b[nb][3] : b[nb][2];
                    MMA_F16(c[mf][nf], a[mf], b0, b1);
                }
            }
        }
        __syncthreads();
    }

    int rq = lane >> 2, cq = (lane & 3) * 2;
    float2 bv[4];
    #pragma unroll
    for (int nf = 0; nf < 4; nf++) {
        int col = n0 + wn * 32 + nf * 8 + cq;
        bv[nf] = make_float2(bias[col], bias[col + 1]);
    }

    #pragma unroll
    for (int mf = 0; mf < 4; mf++) {
        #pragma unroll
        for (int nf = 0; nf < 4; nf++) {
            int r   = m0 + wm * 64 + mf * 16 + rq;
            int col = n0 + wn * 32 + nf * 8 + cq;
            float2 lo = make_float2(c[mf][nf][0] + bv[nf].x, c[mf][nf][1] + bv[nf].y);
            float2 hi = make_float2(c[mf][nf][2] + bv[nf].x, c[mf][nf][3] + bv[nf].y);
            if (mode == 3) {
                *(float2*)(dst_param + (size_t)r * 1024 + col)       = lo;
                *(float2*)(dst_param + (size_t)(r + 8) * 1024 + col) = hi;
            } else {
                float* g = (mode == 0) ? g_Q : (mode == 1) ? g_K : g_V;
                int h = col >> 6, d0 = col & 63;
                int b1 = r >> 11, s1 = r & 2047;
                *(float2*)(g + (((size_t)(b1 * NH + h) * SEQ + s1) << 6) + d0) = lo;
                int s2 = (r + 8) & 2047;
                *(float2*)(g + (((size_t)(b1 * NH + h) * SEQ + s2) << 6) + d0) = hi;
            }
        }
    }
}

// ---------------------------------------------------------------------------
// Fused RoPE + fp16 hi/lo conversion.  blockIdx.y: 0=Q (rope+scale), 1=K (rope),
// 2=V (plain). Q scale = 0.125*log2(e) folds the exp2-domain softmax scale.
// ---------------------------------------------------------------------------
#define QSCALE 0.18033688011112042f   // 0.125 * log2(e)

__global__ void conv_rope()
{
    int gw   = (blockIdx.x * blockDim.x + threadIdx.x) >> 5;
    int lane = threadIdx.x & 31;
    int which = blockIdx.y;
    const float* src = (which == 0) ? g_Q : (which == 1) ? g_K : g_V;
    __half* dh = (which == 0) ? g_Qh : (which == 1) ? g_Kh : g_Vh;
    __half* dl = (which == 0) ? g_Ql : (which == 1) ? g_Kl : g_Vl;
    int s = gw & (SEQ - 1);
    const float* row = src + (size_t)gw * HD;

    float v0, v1;
    if (which < 2) {
        float invf = (float)pow(10000.0, -(double)lane / 32.0);
        float sn, cs;
        sincosf((float)s * invf, &sn, &cs);
        float xe   = row[lane];
        float xe32 = row[lane + 32];
        float x2e  = row[2 * lane];
        float x2e1 = row[2 * lane + 1];
        v0 = xe   * cs - x2e1 * sn;
        v1 = xe32 * cs + x2e  * sn;
        if (which == 0) { v0 *= QSCALE; v1 *= QSCALE; }
    } else {
        v0 = row[lane];
        v1 = row[lane + 32];
    }
    __half h0 = __float2half_rn(v0);
    __half h1 = __float2half_rn(v1);
    size_t o = (size_t)gw * HD;
    dh[o + lane]      = h0;
    dh[o + lane + 32] = h1;
    dl[o + lane]      = __float2half_rn(v0 - __half2float(h0));
    dl[o + lane + 32] = __float2half_rn(v1 - __half2float(h1));
}

// ---------------------------------------------------------------------------
// Flash attention: BM=128 (8 warps), BN=64, pre-converted fp16 hi/lo inputs,
// cp.async double-buffered KV, exp2-domain softmax, P(hi)·V(hi+lo).
// Epilogue emits fp16 hi/lo ctx directly into g_A2 for the output GEMM.
// ---------------------------------------------------------------------------
#define AP 72
#define ROWB (AP*2)
#define PLANE (64*ROWB)          // 9216
#define KVSTAGE (4*PLANE)        // 36864
#define ATTN_SMEM (2*KVSTAGE)    // 73728

__global__ __launch_bounds__(256)
void attn_mma()
{
    extern __shared__ __align__(16) char smb[];
    uint32_t sb = smem_u32(smb);

    int tid  = threadIdx.x;
    int lane = tid & 31;
    int wid  = tid >> 5;                    // 0..7
    int bh   = blockIdx.y;
    int bx   = gridDim.x - 1 - blockIdx.x;  // heaviest CTAs first
    int q0   = bx << 7;
    int nt   = 2 * bx + 2;

    const __half* Qh = g_Qh + (size_t)bh * SEQ * HD;
    const __half* Ql = g_Ql + (size_t)bh * SEQ * HD;
    const __half* Kh = g_Kh + (size_t)bh * SEQ * HD;
    const __half* Kl = g_Kl + (size_t)bh * SEQ * HD;
    const __half* Vh = g_Vh + (size_t)bh * SEQ * HD;
    const __half* Vl = g_Vl + (size_t)bh * SEQ * HD;

    int lr = ((lane >> 3) & 1) * 8 + (lane & 7);
    int lk = (lane >> 4) * 8;
    int rq = lane >> 2, cq = (lane & 3) * 2;

    auto load_kv = [&](int t, int stage) {
        int k0 = t << 6;
        uint32_t base = sb + stage * KVSTAGE;
        #pragma unroll
        for (int it = 0; it < 2; it++) {
            int id = tid + (it << 8);
            int r = id >> 3, ch = id & 7;
            uint32_t o = r * ROWB + (ch << 4);
            int go = ((k0 + r) << 6) + (ch << 3);
            CP_ASYNC16(base + o,             Kh + go);
            CP_ASYNC16(base + PLANE + o,     Kl + go);
            CP_ASYNC16(base + 2*PLANE + o,   Vh + go);
            CP_ASYNC16(base + 3*PLANE + o,   Vl + go);
        }
        CP_COMMIT();
    };

    // prologue: Q into stage0 area, KV(0) into stage1
    #pragma unroll
    for (int it = 0; it < 4; it++) {
        int id = tid + (it << 8);
        int r = id >> 3, ch = id & 7;
        uint32_t o = r * ROWB + (ch << 4);
        int go = ((q0 + r) << 6) + (ch << 3);
        CP_ASYNC16(sb + o,             Qh + go);
        CP_ASYNC16(sb + 2*PLANE + o,   Ql + go);
    }
    CP_COMMIT();
    load_kv(0, 1);
    CP_WAIT0();
    __syncthreads();

    uint32_t qh[4][4], ql[4][4];
    #pragma unroll
    for (int kc = 0; kc < 4; kc++) {
        uint32_t off = (uint32_t)(wid*16 + lr) * ROWB + (kc*16 + lk) * 2;
        LDMATRIX_X4(qh[kc][0], qh[kc][1], qh[kc][2], qh[kc][3], sb + off);
        LDMATRIX_X4(ql[kc][0], ql[kc][1], ql[kc][2], ql[kc][3], sb + 2*PLANE + off);
    }
    __syncthreads();   // Q area free for KV(1)

    float acc[8][4];
    #pragma unroll
    for (int nf = 0; nf < 8; nf++)
        #pragma unroll
        for (int v = 0; v < 4; v++) acc[nf][v] = 0.0f;
    float m_i[2] = {-1e30f, -1e30f};
    float l_i[2] = {0.0f, 0.0f};

    int wminrow = q0 + wid*16;

    #pragma unroll 1
    for (int t = 0; t < nt; t++) {
        int k0 = t << 6;
        if (t + 1 < nt) { load_kv(t + 1, t & 1); CP_WAIT1(); }
        else            { CP_WAIT0(); }
        __syncthreads();

        uint32_t khb = sb + ((t + 1) & 1) * KVSTAGE;
        uint32_t klb = khb + PLANE;
        uint32_t vhb = khb + 2*PLANE;
        uint32_t vlb = khb + 3*PLANE;

        // ---- S = Q K^T (3-term hi/lo) ----
        float sc[8][4];
        #pragma unroll
        for (int nf = 0; nf < 8; nf++)
            #pragma unroll
            for (int v = 0; v < 4; v++) sc[nf][v] = 0.0f;

        #pragma unroll
        for (int kc = 0; kc < 4; kc++) {
            #pragma unroll
            for (int nb = 0; nb < 4; nb++) {
                uint32_t off = (uint32_t)(nb*16 + lr) * ROWB + (kc*16 + lk) * 2;
                uint32_t bh0, bh1, bh2, bh3, bl0, bl1, bl2, bl3;
                LDMATRIX_X4(bh0, bh1, bh2, bh3, khb + off);
                LDMATRIX_X4(bl0, bl1, bl2, bl3, klb + off);
                MMA_F16(sc[2*nb],   qh[kc], bh0, bh2);
                MMA_F16(sc[2*nb],   ql[kc], bh0, bh2);
                MMA_F16(sc[2*nb],   qh[kc], bl0, bl2);
                MMA_F16(sc[2*nb+1], qh[kc], bh1, bh3);
                MMA_F16(sc[2*nb+1], ql[kc], bh1, bh3);
                MMA_F16(sc[2*nb+1], qh[kc], bl1, bl3);
            }
        }

        // ---- causal mask (any warp whose rows can see future cols) ----
        if (k0 + 63 > wminrow) {
            int row0 = wminrow + rq;
            #pragma unroll
            for (int nf = 0; nf < 8; nf++) {
                int col = k0 + nf*8 + cq;
                if (col     > row0)     sc[nf][0] = -1e30f;
                if (col + 1 > row0)     sc[nf][1] = -1e30f;
                if (col     > row0 + 8) sc[nf][2] = -1e30f;
                if (col + 1 > row0 + 8) sc[nf][3] = -1e30f;
            }
        }

        // ---- online softmax in exp2 domain (2 rows per thread) ----
        #pragma unroll
        for (int i = 0; i < 2; i++) {
            float mx = -1e30f;
            #pragma unroll
            for (int nf = 0; nf < 8; nf++)
                mx = fmaxf(mx, fmaxf(sc[nf][2*i], sc[nf][2*i+1]));
            mx = fmaxf(mx, __shfl_xor_sync(0xffffffffu, mx, 1));
            mx = fmaxf(mx, __shfl_xor_sync(0xffffffffu, mx, 2));
            float mnew  = fmaxf(m_i[i], mx);
            float scale = ex2f(m_i[i] - mnew);
            float ls = 0.0f;
            #pragma unroll
            for (int nf = 0; nf < 8; nf++) {
                float p0 = ex2f(sc[nf][2*i]   - mnew);
                float p1 = ex2f(sc[nf][2*i+1] - mnew);
                sc[nf][2*i]   = p0;
                sc[nf][2*i+1] = p1;
                ls += p0 + p1;
            }
            ls += __shfl_xor_sync(0xffffffffu, ls, 1);
            ls += __shfl_xor_sync(0xffffffffu, ls, 2);
            l_i[i] = l_i[i] * scale + ls;
            m_i[i] = mnew;
            #pragma unroll
            for (int nf = 0; nf < 8; nf++) {
                acc[nf][2*i]   *= scale;
                acc[nf][2*i+1] *= scale;
            }
        }

        // ---- ctx += P(hi) * (Vhi + Vlo), P from registers ----
        #pragma unroll
        for (int kc = 0; kc < 4; kc++) {
            uint32_t ph[4];
            ph[0] = h2u(__floats2half2_rn(sc[2*kc][0],   sc[2*kc][1]));
            ph[1] = h2u(__floats2half2_rn(sc[2*kc][2],   sc[2*kc][3]));
            ph[2] = h2u(__floats2half2_rn(sc[2*kc+1][0], sc[2*kc+1][1]));
            ph[3] = h2u(__floats2half2_rn(sc[2*kc+1][2], sc[2*kc+1][3]));
            #pragma unroll
            for (int db = 0; db < 4; db++) {
                uint32_t off = (uint32_t)(kc*16 + (lane & 15)) * ROWB
                             + (db*16 + ((lane >> 4) << 3)) * 2;
                uint32_t vh0, vh1, vh2, vh3, vl0, vl1, vl2, vl3;
                LDMATRIX_X4T(vh0, vh1, vh2, vh3, vhb + off);
                LDMATRIX_X4T(vl0, vl1, vl2, vl3, vlb + off);
                MMA_F16(acc[2*db],   ph, vh0, vh1);
                MMA_F16(acc[2*db],   ph, vl0, vl1);
                MMA_F16(acc[2*db+1], ph, vh2, vh3);
                MMA_F16(acc[2*db+1], ph, vl2, vl3);
            }
        }
        __syncthreads();
    }

    // ---- epilogue: normalize + fp16 hi/lo split straight into g_A2 ----
    // g_A2 row = b*SEQ+s (width 2048: [hi(1024) | lo(1024)]), col = h*64+d.
    int b = bh >> 4, h = bh & 15;
    #pragma unroll
    for (int i = 0; i < 2; i++) {
        float inv = 1.0f / l_i[i];
        int s = q0 + wid*16 + rq + 8*i;
        __half* rowp = g_A2 + ((size_t)(b * SEQ + s) << 11) + (h << 6);
        #pragma unroll
        for (int nf = 0; nf < 8; nf++) {
            float v0 = acc[nf][2*i]   * inv;
            float v1 = acc[nf][2*i+1] * inv;
            __half2 hv = __floats2half2_rn(v0, v1);
            __half2 lv = __floats2half2_rn(v0 - __half2float(__low2half(hv)),
                                           v1 - __half2float(__high2half(hv)));
            *(__half2*)(rowp + nf*8 + cq)        = hv;
            *(__half2*)(rowp + 1024 + nf*8 + cq) = lv;
        }
    }
}

// ---------------------------------------------------------------------------
extern "C" void kernel_launch(void* const* d_in, const int* in_sizes, int n_in,
                              void* d_out, int out_size)
{
    const float* query = (const float*)d_in[0];
    const float* key   = (const float*)d_in[1];
    const float* value = (const float*)d_in[2];
    const float* w_q = (const float*)d_in[4];
    const float* b_q = (const float*)d_in[5];
    const float* w_k = (const float*)d_in[6];
    const float* b_k = (const float*)d_in[7];
    const float* w_v = (const float*)d_in[8];
    const float* b_v = (const float*)d_in[9];
    const float* w_o = (const float*)d_in[10];
    const float* b_o = (const float*)d_in[11];
    float* out = (float*)d_out;

    static int attr_set = 0;
    if (!attr_set) {
        cudaFuncSetAttribute(gemm_mma, cudaFuncAttributeMaxDynamicSharedMemorySize, GEMM_SMEM);
        cudaFuncSetAttribute(attn_mma, cudaFuncAttributeMaxDynamicSharedMemorySize, ATTN_SMEM);
        attr_set = 1;
    }

    dim3 ggrid(DIM / 128, MROWS / 128);   // (8, 64)

    // Launch order puts gemm_mma at index 3 (the launch ncu profiles).
    split_x<<<MROWS, 256>>>(query);                 // 0
    split_w<<<DIM,   256>>>(w_q, 0);                // 1
    split_w<<<DIM,   256>>>(w_o, 1);                // 2 (independent; fills g_B2o)
    gemm_mma<<<ggrid, 256, GEMM_SMEM>>>(b_q, nullptr, 0, 0);  // 3 <- profiled

    split_x<<<MROWS, 256>>>(key);                   // 4
    split_w<<<DIM,   256>>>(w_k, 0);                // 5
    gemm_mma<<<ggrid, 256, GEMM_SMEM>>>(b_k, nullptr, 1, 0);  // 6

    split_x<<<MROWS, 256>>>(value);                 // 7
    split_w<<<DIM,   256>>>(w_v, 0);                // 8
    gemm_mma<<<ggrid, 256, GEMM_SMEM>>>(b_v, nullptr, 2, 0);  // 9

    conv_rope<<<dim3(BATCH*NH*SEQ/8, 3), 256>>>();  // 10
    attn_mma<<<dim3(SEQ/128, BATCH*NH), 256, ATTN_SMEM>>>();  // 11

    gemm_mma<<<ggrid, 256, GEMM_SMEM>>>(b_o, out, 3, 1);      // 12
}

// round 10
// speedup vs baseline: 2.0944x; 1.0713x over previous
#include <cuda_runtime.h>
#include <cuda_fp16.h>
#include <math.h>
#include <stdint.h>

#define BATCH 4
#define SEQ   2048
#define DIM   1024
#define NH    16
#define HD    64
#define MROWS (BATCH*SEQ)

// ---------------------------------------------------------------------------
// Scratch (__device__ globals; allocation-free rule)
// ---------------------------------------------------------------------------
__device__ float g_Q[BATCH*NH*SEQ*HD];
__device__ float g_K[BATCH*NH*SEQ*HD];
__device__ float g_V[BATCH*NH*SEQ*HD];
// fp16x2 GEMM operands: A2 = [Xhi | Xlo] (row width 2048), B = fp16 weights
__device__ __half g_A2[(size_t)MROWS*2048];
__device__ __half g_B2[(size_t)DIM*DIM];
__device__ __half g_B2o[(size_t)DIM*DIM];
// fp16 hi/lo planes for attention (RoPE + scale pre-applied to Q/K)
__device__ __half g_Qh[BATCH*NH*SEQ*HD];
__device__ __half g_Ql[BATCH*NH*SEQ*HD];
__device__ __half g_Kh[BATCH*NH*SEQ*HD];
__device__ __half g_Kl[BATCH*NH*SEQ*HD];
__device__ __half g_Vh[BATCH*NH*SEQ*HD];
__device__ __half g_Vl[BATCH*NH*SEQ*HD];

__device__ __forceinline__ uint32_t smem_u32(const void* p) {
    uint32_t a;
    asm("{ .reg .u64 t; cvta.to.shared.u64 t, %1; cvt.u32.u64 %0, t; }" : "=r"(a) : "l"(p));
    return a;
}

#define LDMATRIX_X4(r0, r1, r2, r3, addr) \
    asm volatile("ldmatrix.sync.aligned.m8n8.x4.shared.b16 {%0,%1,%2,%3}, [%4];" \
        : "=r"(r0), "=r"(r1), "=r"(r2), "=r"(r3) : "r"(addr))

#define LDMATRIX_X4T(r0, r1, r2, r3, addr) \
    asm volatile("ldmatrix.sync.aligned.m8n8.x4.trans.shared.b16 {%0,%1,%2,%3}, [%4];" \
        : "=r"(r0), "=r"(r1), "=r"(r2), "=r"(r3) : "r"(addr))

#define MMA_F16(c, a, b0v, b1v) \
    asm volatile("mma.sync.aligned.m16n8k16.row.col.f32.f16.f16.f32 " \
        "{%0,%1,%2,%3}, {%4,%5,%6,%7}, {%8,%9}, {%0,%1,%2,%3};" \
        : "+f"((c)[0]), "+f"((c)[1]), "+f"((c)[2]), "+f"((c)[3]) \
        : "r"((a)[0]), "r"((a)[1]), "r"((a)[2]), "r"((a)[3]), "r"(b0v), "r"(b1v))

#define CP_ASYNC16(dst, src) \
    asm volatile("cp.async.cg.shared.global [%0], [%1], 16;" :: "r"(dst), "l"(src))
#define CP_COMMIT() asm volatile("cp.async.commit_group;" ::: "memory")
#define CP_WAIT0()  asm volatile("cp.async.wait_group 0;" ::: "memory")
#define CP_WAIT1()  asm volatile("cp.async.wait_group 1;" ::: "memory")

__device__ __forceinline__ uint32_t h2u(__half2 h) { return *reinterpret_cast<uint32_t*>(&h); }
__device__ __forceinline__ float ex2f(float x) {
    float y; asm("ex2.approx.f32 %0, %1;" : "=f"(y) : "f"(x)); return y;
}

struct h4 { __half2 a, b; };

// ---------------------------------------------------------------------------
// X split: f32 -> fp16 hi/lo into g_A2 (row 2048: [hi(1024) | lo(1024)])
// ---------------------------------------------------------------------------
__global__ void split_x(const float* __restrict__ in)
{
    int i = blockIdx.x * blockDim.x + threadIdx.x;   // float4 index
    if (i >= MROWS * 256) return;
    int r = i >> 8, c4 = i & 255;
    float4 v = ((const float4*)in)[i];
    __half2 h01 = __floats2half2_rn(v.x, v.y);
    __half2 h23 = __floats2half2_rn(v.z, v.w);
    __half2 l01 = __floats2half2_rn(v.x - __half2float(__low2half(h01)),
                                    v.y - __half2float(__high2half(h01)));
    __half2 l23 = __floats2half2_rn(v.z - __half2float(__low2half(h23)),
                                    v.w - __half2float(__high2half(h23)));
    size_t base = (size_t)r * 2048 + c4 * 4;
    h4 hv; hv.a = h01; hv.b = h23;
    h4 lv; lv.a = l01; lv.b = l23;
    *(h4*)(g_A2 + base)        = hv;
    *(h4*)(g_A2 + base + 1024) = lv;
}

// ---------------------------------------------------------------------------
// W convert: f32 -> fp16 (row 1024). which: 0 -> g_B2, 1 -> g_B2o
// ---------------------------------------------------------------------------
__global__ void split_w(const float* __restrict__ in, int which)
{
    int i = blockIdx.x * blockDim.x + threadIdx.x;   // float4 index
    if (i >= DIM * 256) return;
    float4 v = ((const float4*)in)[i];
    h4 hv;
    hv.a = __floats2half2_rn(v.x, v.y);
    hv.b = __floats2half2_rn(v.z, v.w);
    __half* out = which ? g_B2o : g_B2;
    *(h4*)(out + (size_t)i * 4) = hv;
}

// ---------------------------------------------------------------------------
// mma.sync fp16x2 GEMM: C[8192x1024] = (Xhi+Xlo) @ W^T + bias over K'=2048
// CTA 128x128, 8 warps (2m x 4n), warp tile 64x32, m16n8k16 HMMA.
// BK=64, cp.async double buffered. Pitch 72 halfs (144B) -> conflict-free.
// ---------------------------------------------------------------------------
#define NST      32
#define STAGE_B  (128*144)
#define GEMM_SMEM (4*STAGE_B)            // 73728

__global__ __launch_bounds__(256)
void gemm_mma(const float* __restrict__ bias, float* __restrict__ dst_param,
              int mode, int bsel)
{
    extern __shared__ __align__(16) char sm[];
    uint32_t sb = smem_u32(sm);

    const __half* Bmat = bsel ? g_B2o : g_B2;

    int tid  = threadIdx.x;
    int lane = tid & 31;
    int wid  = tid >> 5;
    int wm   = wid & 1;
    int wn   = wid >> 1;
    int m0 = blockIdx.y << 7, n0 = blockIdx.x << 7;

    int lr = ((lane >> 3) & 1) * 8 + (lane & 7);
    int lk = (lane >> 4) * 8;

    float c[4][4][4];
    #pragma unroll
    for (int mf = 0; mf < 4; mf++)
        #pragma unroll
        for (int nf = 0; nf < 4; nf++)
            #pragma unroll
            for (int v = 0; v < 4; v++) c[mf][nf][v] = 0.0f;

    auto load_stage = [&](int t, int buf) {
        int kp = t << 6;                  // A col in [0,2048)
        int bc = kp & 1023;               // B col in [0,1024)
        const __half* Ab = g_A2 + (size_t)m0 * 2048 + kp;
        const __half* Bb = Bmat + (size_t)n0 * 1024 + bc;
        uint32_t sa  = sb + buf * STAGE_B;
        uint32_t sbb = sb + 2 * STAGE_B + buf * STAGE_B;
        #pragma unroll
        for (int it = 0; it < 4; it++) {
            int id = tid + (it << 8);
            int r = id >> 3, ch = id & 7;
            CP_ASYNC16(sa  + r * 144 + (ch << 4), Ab + (size_t)r * 2048 + (ch << 3));
            CP_ASYNC16(sbb + r * 144 + (ch << 4), Bb + (size_t)r * 1024 + (ch << 3));
        }
        CP_COMMIT();
    };

    load_stage(0, 0);

    #pragma unroll 1
    for (int t = 0; t < NST; t++) {
        CP_WAIT0();
        __syncthreads();
        if (t + 1 < NST) load_stage(t + 1, (t + 1) & 1);

        uint32_t sa  = sb + (t & 1) * STAGE_B;
        uint32_t sbb = sb + 2 * STAGE_B + (t & 1) * STAGE_B;

        #pragma unroll
        for (int kk = 0; kk < 64; kk += 16) {
            uint32_t a[4][4];
            #pragma unroll
            for (int mf = 0; mf < 4; mf++) {
                uint32_t ad = sa + (uint32_t)(wm * 64 + mf * 16 + lr) * 144 + (kk + lk) * 2;
                LDMATRIX_X4(a[mf][0], a[mf][1], a[mf][2], a[mf][3], ad);
            }
            uint32_t b[2][4];
            #pragma unroll
            for (int nb = 0; nb < 2; nb++) {
                uint32_t bd = sbb + (uint32_t)(wn * 32 + nb * 16 + lr) * 144 + (kk + lk) * 2;
                LDMATRIX_X4(b[nb][0], b[nb][1], b[nb][2], b[nb][3], bd);
            }
            #pragma unroll
            for (int mf = 0; mf < 4; mf++) {
                #pragma unroll
                for (int nf = 0; nf < 4; nf++) {
                    int nb = nf >> 1;
                    uint32_t b0 = (nf & 1) ? b[nb][1] : b[nb][0];
                    uint32_t b1 = (nf & 1) ? b[nb][3] : b[nb][2];
                    MMA_F16(c[mf][nf], a[mf], b0, b1);
                }
            }
        }
        __syncthreads();
    }

    int rq = lane >> 2, cq = (lane & 3) * 2;
    float2 bv[4];
    #pragma unroll
    for (int nf = 0; nf < 4; nf++) {
        int col = n0 + wn * 32 + nf * 8 + cq;
        bv[nf] = make_float2(bias[col], bias[col + 1]);
    }

    #pragma unroll
    for (int mf = 0; mf < 4; mf++) {
        #pragma unroll
        for (int nf = 0; nf < 4; nf++) {
            int r   = m0 + wm * 64 + mf * 16 + rq;
            int col = n0 + wn * 32 + nf * 8 + cq;
            float2 lo = make_float2(c[mf][nf][0] + bv[nf].x, c[mf][nf][1] + bv[nf].y);
            float2 hi = make_float2(c[mf][nf][2] + bv[nf].x, c[mf][nf][3] + bv[nf].y);
            if (mode == 3) {
                *(float2*)(dst_param + (size_t)r * 1024 + col)       = lo;
                *(float2*)(dst_param + (size_t)(r + 8) * 1024 + col) = hi;
            } else {
                float* g = (mode == 0) ? g_Q : (mode == 1) ? g_K : g_V;
                int h = col >> 6, d0 = col & 63;
                int b1 = r >> 11, s1 = r & 2047;
                *(float2*)(g + (((size_t)(b1 * NH + h) * SEQ + s1) << 6) + d0) = lo;
                int s2 = (r + 8) & 2047;
                *(float2*)(g + (((size_t)(b1 * NH + h) * SEQ + s2) << 6) + d0) = hi;
            }
        }
    }
}

// ---------------------------------------------------------------------------
// Fused RoPE + fp16 hi/lo conversion.  blockIdx.y: 0=Q (rope+scale), 1=K (rope),
// 2=V (plain). Q scale = 0.125*log2(e) folds the exp2-domain softmax scale.
// ---------------------------------------------------------------------------
#define QSCALE 0.18033688011112042f   // 0.125 * log2(e)

__global__ void conv_rope()
{
    int gw   = (blockIdx.x * blockDim.x + threadIdx.x) >> 5;
    int lane = threadIdx.x & 31;
    int which = blockIdx.y;
    const float* src = (which == 0) ? g_Q : (which == 1) ? g_K : g_V;
    __half* dh = (which == 0) ? g_Qh : (which == 1) ? g_Kh : g_Vh;
    __half* dl = (which == 0) ? g_Ql : (which == 1) ? g_Kl : g_Vl;
    int s = gw & (SEQ - 1);
    const float* row = src + (size_t)gw * HD;

    float v0, v1;
    if (which < 2) {
        float invf = (float)pow(10000.0, -(double)lane / 32.0);
        float sn, cs;
        sincosf((float)s * invf, &sn, &cs);
        float xe   = row[lane];
        float xe32 = row[lane + 32];
        float x2e  = row[2 * lane];
        float x2e1 = row[2 * lane + 1];
        v0 = xe   * cs - x2e1 * sn;
        v1 = xe32 * cs + x2e  * sn;
        if (which == 0) { v0 *= QSCALE; v1 *= QSCALE; }
    } else {
        v0 = row[lane];
        v1 = row[lane + 32];
    }
    __half h0 = __float2half_rn(v0);
    __half h1 = __float2half_rn(v1);
    size_t o = (size_t)gw * HD;
    dh[o + lane]      = h0;
    dh[o + lane + 32] = h1;
    dl[o + lane]      = __float2half_rn(v0 - __half2float(h0));
    dl[o + lane + 32] = __float2half_rn(v1 - __half2float(h1));
}

// ---------------------------------------------------------------------------
// Flash attention: BM=128 (8 warps), BN=64, cp.async double-buffered KV.
// R10 softmax: exp2 computed as ex2.approx.f16x2 (one MUFU per 2 elems;
// B=+8 bias cancels in normalization), row sums via ones-column MMA in
// exact f32 (no shfl/FADD sum tree). P fragments come straight out of the
// packed ex2 output. Epilogue emits fp16 hi/lo ctx into g_A2.
// ---------------------------------------------------------------------------
#define AP 72
#define ROWB (AP*2)
#define PLANE (64*ROWB)          // 9216
#define KVSTAGE (4*PLANE)        // 36864
#define ATTN_SMEM (2*KVSTAGE)    // 73728
#define ONE2 0x3C003C00u         // half2(1,1)

__global__ __launch_bounds__(256)
void attn_mma()
{
    extern __shared__ __align__(16) char smb[];
    uint32_t sb = smem_u32(smb);

    int tid  = threadIdx.x;
    int lane = tid & 31;
    int wid  = tid >> 5;                    // 0..7
    int bh   = blockIdx.y;
    int bx   = gridDim.x - 1 - blockIdx.x;  // heaviest CTAs first
    int q0   = bx << 7;
    int nt   = 2 * bx + 2;

    const __half* Qh = g_Qh + (size_t)bh * SEQ * HD;
    const __half* Ql = g_Ql + (size_t)bh * SEQ * HD;
    const __half* Kh = g_Kh + (size_t)bh * SEQ * HD;
    const __half* Kl = g_Kl + (size_t)bh * SEQ * HD;
    const __half* Vh = g_Vh + (size_t)bh * SEQ * HD;
    const __half* Vl = g_Vl + (size_t)bh * SEQ * HD;

    int lr = ((lane >> 3) & 1) * 8 + (lane & 7);
    int lk = (lane >> 4) * 8;
    int rq = lane >> 2, cq = (lane & 3) * 2;

    auto load_kv = [&](int t, int stage) {
        int k0 = t << 6;
        uint32_t base = sb + stage * KVSTAGE;
        #pragma unroll
        for (int it = 0; it < 2; it++) {
            int id = tid + (it << 8);
            int r = id >> 3, ch = id & 7;
            uint32_t o = r * ROWB + (ch << 4);
            int go = ((k0 + r) << 6) + (ch << 3);
            CP_ASYNC16(base + o,             Kh + go);
            CP_ASYNC16(base + PLANE + o,     Kl + go);
            CP_ASYNC16(base + 2*PLANE + o,   Vh + go);
            CP_ASYNC16(base + 3*PLANE + o,   Vl + go);
        }
        CP_COMMIT();
    };

    // prologue: Q into stage0 area, KV(0) into stage1
    #pragma unroll
    for (int it = 0; it < 4; it++) {
        int id = tid + (it << 8);
        int r = id >> 3, ch = id & 7;
        uint32_t o = r * ROWB + (ch << 4);
        int go = ((q0 + r) << 6) + (ch << 3);
        CP_ASYNC16(sb + o,             Qh + go);
        CP_ASYNC16(sb + 2*PLANE + o,   Ql + go);
    }
    CP_COMMIT();
    load_kv(0, 1);
    CP_WAIT0();
    __syncthreads();

    uint32_t qh[4][4], ql[4][4];
    #pragma unroll
    for (int kc = 0; kc < 4; kc++) {
        uint32_t off = (uint32_t)(wid*16 + lr) * ROWB + (kc*16 + lk) * 2;
        LDMATRIX_X4(qh[kc][0], qh[kc][1], qh[kc][2], qh[kc][3], sb + off);
        LDMATRIX_X4(ql[kc][0], ql[kc][1], ql[kc][2], ql[kc][3], sb + 2*PLANE + off);
    }
    __syncthreads();   // Q area free for KV(1)

    float acc[8][4];
    #pragma unroll
    for (int nf = 0; nf < 8; nf++)
        #pragma unroll
        for (int v = 0; v < 4; v++) acc[nf][v] = 0.0f;
    float lacc[4] = {0.0f, 0.0f, 0.0f, 0.0f};   // ones-MMA row sums (x2^8)
    float m_i[2] = {-1e30f, -1e30f};

    int wminrow = q0 + wid*16;

    #pragma unroll 1
    for (int t = 0; t < nt; t++) {
        int k0 = t << 6;
        if (t + 1 < nt) { load_kv(t + 1, t & 1); CP_WAIT1(); }
        else            { CP_WAIT0(); }
        __syncthreads();

        uint32_t khb = sb + ((t + 1) & 1) * KVSTAGE;
        uint32_t klb = khb + PLANE;
        uint32_t vhb = khb + 2*PLANE;
        uint32_t vlb = khb + 3*PLANE;

        // ---- S = Q K^T (3-term hi/lo) ----
        float sc[8][4];
        #pragma unroll
        for (int nf = 0; nf < 8; nf++)
            #pragma unroll
            for (int v = 0; v < 4; v++) sc[nf][v] = 0.0f;

        #pragma unroll
        for (int kc = 0; kc < 4; kc++) {
            #pragma unroll
            for (int nb = 0; nb < 4; nb++) {
                uint32_t off = (uint32_t)(nb*16 + lr) * ROWB + (kc*16 + lk) * 2;
                uint32_t bh0, bh1, bh2, bh3, bl0, bl1, bl2, bl3;
                LDMATRIX_X4(bh0, bh1, bh2, bh3, khb + off);
                LDMATRIX_X4(bl0, bl1, bl2, bl3, klb + off);
                MMA_F16(sc[2*nb],   qh[kc], bh0, bh2);
                MMA_F16(sc[2*nb],   ql[kc], bh0, bh2);
                MMA_F16(sc[2*nb],   qh[kc], bl0, bl2);
                MMA_F16(sc[2*nb+1], qh[kc], bh1, bh3);
                MMA_F16(sc[2*nb+1], ql[kc], bh1, bh3);
                MMA_F16(sc[2*nb+1], qh[kc], bl1, bl3);
            }
        }

        // ---- causal mask ----
        if (k0 + 63 > wminrow) {
            int row0 = wminrow + rq;
            #pragma unroll
            for (int nf = 0; nf < 8; nf++) {
                int col = k0 + nf*8 + cq;
                if (col     > row0)     sc[nf][0] = -1e30f;
                if (col + 1 > row0)     sc[nf][1] = -1e30f;
                if (col     > row0 + 8) sc[nf][2] = -1e30f;
                if (col + 1 > row0 + 8) sc[nf][3] = -1e30f;
            }
        }

        // ---- online softmax: packed f16x2 exp2, bias B=+8 (cancels) ----
        uint32_t pr[8][2];
        #pragma unroll
        for (int i = 0; i < 2; i++) {
            float mx = -1e30f;
            #pragma unroll
            for (int nf = 0; nf < 8; nf++)
                mx = fmaxf(mx, fmaxf(sc[nf][2*i], sc[nf][2*i+1]));
            mx = fmaxf(mx, __shfl_xor_sync(0xffffffffu, mx, 1));
            mx = fmaxf(mx, __shfl_xor_sync(0xffffffffu, mx, 2));
            float mnew  = fmaxf(m_i[i], mx);
            float scale = ex2f(m_i[i] - mnew);
            float nb    = 8.0f - mnew;
            #pragma unroll
            for (int nf = 0; nf < 8; nf++) {
                float s0 = sc[nf][2*i]   + nb;
                float s1 = sc[nf][2*i+1] + nb;
                uint32_t pk;
                asm("cvt.rn.f16x2.f32 %0, %1, %2;" : "=r"(pk) : "f"(s1), "f"(s0));
                asm("ex2.approx.f16x2 %0, %1;" : "=r"(pr[nf][i]) : "r"(pk));
            }
            m_i[i] = mnew;
            lacc[2*i]   *= scale;
            lacc[2*i+1] *= scale;
            #pragma unroll
            for (int nf = 0; nf < 8; nf++) {
                acc[nf][2*i]   *= scale;
                acc[nf][2*i+1] *= scale;
            }
        }

        // ---- ctx += P * (Vhi + Vlo); row sums via ones-MMA ----
        #pragma unroll
        for (int kc = 0; kc < 4; kc++) {
            uint32_t ph[4] = { pr[2*kc][0], pr[2*kc][1], pr[2*kc+1][0], pr[2*kc+1][1] };
            MMA_F16(lacc, ph, ONE2, ONE2);
            #pragma unroll
            for (int db = 0; db < 4; db++) {
                uint32_t off = (uint32_t)(kc*16 + (lane & 15)) * ROWB
                             + (db*16 + ((lane >> 4) << 3)) * 2;
                uint32_t vh0, vh1, vh2, vh3, vl0, vl1, vl2, vl3;
                LDMATRIX_X4T(vh0, vh1, vh2, vh3, vhb + off);
                LDMATRIX_X4T(vl0, vl1, vl2, vl3, vlb + off);
                MMA_F16(acc[2*db],   ph, vh0, vh1);
                MMA_F16(acc[2*db],   ph, vl0, vl1);
                MMA_F16(acc[2*db+1], ph, vh2, vh3);
                MMA_F16(acc[2*db+1], ph, vl2, vl3);
            }
        }
        __syncthreads();
    }

    // ---- epilogue: normalize + fp16 hi/lo split straight into g_A2 ----
    int b = bh >> 4, h = bh & 15;
    #pragma unroll
    for (int i = 0; i < 2; i++) {
        float inv = 1.0f / lacc[2*i];
        int s = q0 + wid*16 + rq + 8*i;
        __half* rowp = g_A2 + ((size_t)(b * SEQ + s) << 11) + (h << 6);
        #pragma unroll
        for (int nf = 0; nf < 8; nf++) {
            float v0 = acc[nf][2*i]   * inv;
            float v1 = acc[nf][2*i+1] * inv;
            __half2 hv = __floats2half2_rn(v0, v1);
            __half2 lv = __floats2half2_rn(v0 - __half2float(__low2half(hv)),
                                           v1 - __half2float(__high2half(hv)));
            *(__half2*)(rowp + nf*8 + cq)        = hv;
            *(__half2*)(rowp + 1024 + nf*8 + cq) = lv;
        }
    }
}

// ---------------------------------------------------------------------------
extern "C" void kernel_launch(void* const* d_in, const int* in_sizes, int n_in,
                              void* d_out, int out_size)
{
    const float* query = (const float*)d_in[0];
    const float* key   = (const float*)d_in[1];
    const float* value = (const float*)d_in[2];
    const float* w_q = (const float*)d_in[4];
    const float* b_q = (const float*)d_in[5];
    const float* w_k = (const float*)d_in[6];
    const float* b_k = (const float*)d_in[7];
    const float* w_v = (const float*)d_in[8];
    const float* b_v = (const float*)d_in[9];
    const float* w_o = (const float*)d_in[10];
    const float* b_o = (const float*)d_in[11];
    float* out = (float*)d_out;

    static int attr_set = 0;
    if (!attr_set) {
        cudaFuncSetAttribute(gemm_mma, cudaFuncAttributeMaxDynamicSharedMemorySize, GEMM_SMEM);
        cudaFuncSetAttribute(attn_mma, cudaFuncAttributeMaxDynamicSharedMemorySize, ATTN_SMEM);
        attr_set = 1;
    }

    dim3 ggrid(DIM / 128, MROWS / 128);   // (8, 64)

    split_x<<<MROWS, 256>>>(query);                 // 0
    split_w<<<DIM,   256>>>(w_q, 0);                // 1
    split_w<<<DIM,   256>>>(w_o, 1);                // 2
    gemm_mma<<<ggrid, 256, GEMM_SMEM>>>(b_q, nullptr, 0, 0);  // 3 <- profiled

    split_x<<<MROWS, 256>>>(key);                   // 4
    split_w<<<DIM,   256>>>(w_k, 0);                // 5
    gemm_mma<<<ggrid, 256, GEMM_SMEM>>>(b_k, nullptr, 1, 0);  // 6

    split_x<<<MROWS, 256>>>(value);                 // 7
    split_w<<<DIM,   256>>>(w_v, 0);                // 8
    gemm_mma<<<ggrid, 256, GEMM_SMEM>>>(b_v, nullptr, 2, 0);  // 9

    conv_rope<<<dim3(BATCH*NH*SEQ/8, 3), 256>>>();  // 10
    attn_mma<<<dim3(SEQ/128, BATCH*NH), 256, ATTN_SMEM>>>();  // 11

    gemm_mma<<<ggrid, 256, GEMM_SMEM>>>(b_o, out, 3, 1);      // 12
}